// round 5
// baseline (speedup 1.0000x reference)
#include <cuda_runtime.h>
#include <math.h>
#include <float.h>

#define NMAX 50000
#define EMAX 400000

// Scratch (allocation-free rule: __device__ globals)
__device__ float g_h[NMAX * 128];
__device__ float g_u[NMAX * 128];
__device__ float g_v[NMAX * 128];
__device__ float g_aggr[NMAX * 128];
__device__ float g_s[EMAX];        // scores, then p=exp(s-max) in place
__device__ int   g_eid[EMAX];      // CSR edge ids
__device__ int   g_deg[NMAX];      // degree histogram
__device__ int   g_off[NMAX + 1];  // CSR offsets (mutated by fill)
__device__ unsigned int g_maxkey;
__device__ float g_sum;
// composite weights
__device__ float g_Wcu[64 * 128], g_Wcv[64 * 128];
__device__ float g_bcu[128], g_bcv[128];
__device__ float g_W1y[64 * 64], g_b1y[64];
__device__ float g_W1a[64 * 64], g_b1a[64];

// --- monotonic float<->uint key for atomicMax over signed floats ---
__device__ __forceinline__ unsigned fkey(float f) {
    unsigned b = __float_as_uint(f);
    return (b & 0x80000000u) ? ~b : (b | 0x80000000u);
}
__device__ __forceinline__ float fdecode(unsigned k) {
    return __uint_as_float((k & 0x80000000u) ? (k ^ 0x80000000u) : ~k);
}

// ---------------------------------------------------------------------------
__global__ void init_k(int n) {
    int i = blockIdx.x * blockDim.x + threadIdx.x;
    if (i == 0) { g_maxkey = 0u; g_sum = 0.f; }
    for (; i < n; i += gridDim.x * blockDim.x) g_deg[i] = 0;
}

// ---------------------------------------------------------------------------
// Composite attention projections:
//   g_Wcu = W_node @ W_att1[0:128]      g_bcu = b_node @ W_att1[0:128]
//   g_Wcv = W_node @ W_att1[128:256]    g_bcv = b_node @ W_att1[128:256]
// ---------------------------------------------------------------------------
__global__ void compose_uv_k(const float* __restrict__ Wn, const float* __restrict__ bn,
                             const float* __restrict__ Watt) {
    int id = blockIdx.x * blockDim.x + threadIdx.x;
    if (id < 8192) {                       // Wcu
        int f = id >> 7, j = id & 127;
        float a = 0.f;
        for (int m = 0; m < 128; m++) a += Wn[f * 128 + m] * Watt[m * 128 + j];
        g_Wcu[f * 128 + j] = a;
    } else if (id < 16384) {               // Wcv
        int k = id - 8192, f = k >> 7, j = k & 127;
        float a = 0.f;
        for (int m = 0; m < 128; m++) a += Wn[f * 128 + m] * Watt[(128 + m) * 128 + j];
        g_Wcv[f * 128 + j] = a;
    } else if (id < 16512) {               // bcu
        int j = id - 16384;
        float a = 0.f;
        for (int m = 0; m < 128; m++) a += bn[m] * Watt[m * 128 + j];
        g_bcu[j] = a;
    } else if (id < 16640) {               // bcv
        int j = id - 16512;
        float a = 0.f;
        for (int m = 0; m < 128; m++) a += bn[m] * Watt[(128 + m) * 128 + j];
        g_bcv[j] = a;
    }
}

// Composite head layer1: W1c = W_node @ Wy1 [64,64], b1c = b_node@Wy1 + by1
__global__ void compose_head_k(const float* __restrict__ Wn, const float* __restrict__ bn,
                               const float* __restrict__ W1, const float* __restrict__ b1,
                               float* __restrict__ outW, float* __restrict__ outb) {
    int id = blockIdx.x * blockDim.x + threadIdx.x;
    if (id < 4096) {
        int f = id >> 6, j = id & 63;
        float a = 0.f;
        for (int m = 0; m < 128; m++) a += Wn[f * 128 + m] * W1[m * 64 + j];
        outW[f * 64 + j] = a;
    } else if (id < 4160) {
        int j = id - 4096;
        float a = b1[j];
        for (int m = 0; m < 128; m++) a += bn[m] * W1[m * 64 + j];
        outb[j] = a;
    }
}

// ---------------------------------------------------------------------------
// Fused encoder: from mol_x [n,64] compute h, u, v (each [n,128]) in one pass.
// Weights: W_node, g_Wcu, g_Wcv staged in smem (3 x 64x128), X staged once.
// ---------------------------------------------------------------------------
__global__ void __launch_bounds__(128)
enc_k(const float* __restrict__ X, const float* __restrict__ Wn,
      const float* __restrict__ bn, int n) {
    extern __shared__ float sm[];
    float* Ws = sm;            // 3 * 8192
    float* bs = sm + 24576;    // 3 * 128
    float* Xs = bs + 384;      // 32 * 64
    int t = threadIdx.x;
    for (int i = t; i < 2048; i += 128) ((float4*)Ws)[i]           = ((const float4*)Wn)[i];
    for (int i = t; i < 2048; i += 128) ((float4*)(Ws + 8192))[i]  = ((const float4*)g_Wcu)[i];
    for (int i = t; i < 2048; i += 128) ((float4*)(Ws + 16384))[i] = ((const float4*)g_Wcv)[i];
    bs[t] = bn[t]; bs[128 + t] = g_bcu[t]; bs[256 + t] = g_bcv[t];

    for (int row0 = blockIdx.x * 32; row0 < n; row0 += gridDim.x * 32) {
        int nr = min(32, n - row0);
        __syncthreads();
        for (int i = t; i < nr * 16; i += 128)
            ((float4*)Xs)[i] = ((const float4*)(X + (size_t)row0 * 64))[i];
        __syncthreads();

#pragma unroll 1
        for (int g = 0; g < 3; g++) {
            const float* Wg = Ws + g * 8192;
            float acc[32];
#pragma unroll
            for (int r = 0; r < 32; r++) acc[r] = 0.f;
            for (int k4 = 0; k4 < 64; k4 += 4) {
                float w0 = Wg[(k4 + 0) * 128 + t];
                float w1 = Wg[(k4 + 1) * 128 + t];
                float w2 = Wg[(k4 + 2) * 128 + t];
                float w3 = Wg[(k4 + 3) * 128 + t];
#pragma unroll
                for (int r = 0; r < 32; r++) {
                    float4 xv = *(const float4*)&Xs[r * 64 + k4];
                    acc[r] += xv.x * w0 + xv.y * w1 + xv.z * w2 + xv.w * w3;
                }
            }
            float bv = bs[g * 128 + t];
            float* O = (g == 0) ? g_h : (g == 1) ? g_u : g_v;
            for (int r = 0; r < nr; r++)
                O[(size_t)(row0 + r) * 128 + t] = acc[r] + bv;
        }
    }
}

// ---------------------------------------------------------------------------
// GEMM (persistent): Y = (X[n,128] @ W[128,128]) * scale + bias
// ---------------------------------------------------------------------------
__global__ void __launch_bounds__(128)
gemm_k(const float* __restrict__ X, const float* __restrict__ W,
       const float* __restrict__ bias, float* __restrict__ Y,
       int n, const float* __restrict__ sumptr) {
    extern __shared__ float sm[];
    float* Ws = sm;            // 128*128
    float* Xs = sm + 16384;    // 32*128
    int t = threadIdx.x;
    for (int i = t; i < 4096; i += 128) ((float4*)Ws)[i] = ((const float4*)W)[i];
    float bv = bias[t];

    for (int row0 = blockIdx.x * 32; row0 < n; row0 += gridDim.x * 32) {
        int nr = min(32, n - row0);
        __syncthreads();
        for (int i = t; i < nr * 32; i += 128)
            ((float4*)Xs)[i] = ((const float4*)(X + (size_t)row0 * 128))[i];
        __syncthreads();

        float acc[32];
#pragma unroll
        for (int r = 0; r < 32; r++) acc[r] = 0.f;
        for (int k4 = 0; k4 < 128; k4 += 4) {
            float w0 = Ws[(k4 + 0) * 128 + t];
            float w1 = Ws[(k4 + 1) * 128 + t];
            float w2 = Ws[(k4 + 2) * 128 + t];
            float w3 = Ws[(k4 + 3) * 128 + t];
#pragma unroll
            for (int r = 0; r < 32; r++) {
                float4 xv = *(const float4*)&Xs[r * 128 + k4];
                acc[r] += xv.x * w0 + xv.y * w1 + xv.z * w2 + xv.w * w3;
            }
        }
        float scale = sumptr ? (1.f / *sumptr) : 1.f;
        for (int r = 0; r < nr; r++)
            Y[(size_t)(row0 + r) * 128 + t] = acc[r] * scale + bv;
    }
}

// ---------------------------------------------------------------------------
// CSR build: histogram + single-block scan + fill (exp/sum fused into fill)
// ---------------------------------------------------------------------------
__global__ void hist_k(const int* __restrict__ dst, int E) {
    for (int i = blockIdx.x * blockDim.x + threadIdx.x; i < E; i += gridDim.x * blockDim.x)
        atomicAdd(&g_deg[dst[i]], 1);
}

__global__ void scan_k(int n) {
    __shared__ int warp_sums[32];
    __shared__ int s_carry;
    int t = threadIdx.x, lane = t & 31, wid = t >> 5;
    if (t == 0) s_carry = 0;
    __syncthreads();
    for (int base = 0; base < n; base += 1024) {
        int i = base + t;
        int v = (i < n) ? g_deg[i] : 0;
        int x = v;
        for (int o = 1; o < 32; o <<= 1) {
            int y = __shfl_up_sync(0xffffffffu, x, o);
            if (lane >= o) x += y;
        }
        if (lane == 31) warp_sums[wid] = x;
        __syncthreads();
        if (wid == 0) {
            int w = warp_sums[lane];
            for (int o = 1; o < 32; o <<= 1) {
                int y = __shfl_up_sync(0xffffffffu, w, o);
                if (lane >= o) w += y;
            }
            warp_sums[lane] = w;
        }
        __syncthreads();
        int excl = s_carry + (wid ? warp_sums[wid - 1] : 0) + x - v;
        if (i < n) g_off[i] = excl;
        int btot = warp_sums[31];
        __syncthreads();
        if (t == 0) s_carry += btot;
        __syncthreads();
    }
    if (t == 0) g_off[n] = s_carry;
}

// fill: p = exp(s-max) in place, accumulate g_sum, slot edges into CSR.
// Uses atomicAdd on g_off itself: after this kernel g_off[d] == original
// g_off[d+1], so node d's range is [d ? g_off[d-1] : 0, g_off[d]).
__global__ void fill_k(const int* __restrict__ dst, int E) {
    float mx = fdecode(g_maxkey);
    float loc = 0.f;
    for (int i = blockIdx.x * blockDim.x + threadIdx.x; i < E; i += gridDim.x * blockDim.x) {
        float p = expf(g_s[i] - mx);
        g_s[i] = p;
        loc += p;
        int slot = atomicAdd(&g_off[dst[i]], 1);
        g_eid[slot] = i;
    }
    for (int o = 16; o; o >>= 1) loc += __shfl_xor_sync(0xffffffffu, loc, o);
    __shared__ float ws[8];
    int lane = threadIdx.x & 31, wid = threadIdx.x >> 5;
    if (lane == 0) ws[wid] = loc;
    __syncthreads();
    if (threadIdx.x == 0) {
        float tot = 0.f;
        for (int i = 0; i < (blockDim.x >> 5); i++) tot += ws[i];
        atomicAdd(&g_sum, tot);
    }
}

// ---------------------------------------------------------------------------
// Edge attention score + fused global max. Persistent: warps loop over edges,
// attention weights loaded into registers ONCE per warp.
// ---------------------------------------------------------------------------
__global__ void edge_k(const int* __restrict__ src, const int* __restrict__ dst,
                       const float* __restrict__ pos,
                       const float* __restrict__ Wd, const float* __restrict__ b1,
                       const float* __restrict__ W2, const float* __restrict__ b2,
                       int E) {
    int lane = threadIdx.x & 31;
    int wid = threadIdx.x >> 5;
    int gw = (blockIdx.x * blockDim.x + threadIdx.x) >> 5;
    int nw = (gridDim.x * blockDim.x) >> 5;

    float4 c0 = ((const float4*)Wd)[lane];
    float4 c1 = ((const float4*)(Wd + 128))[lane];
    float4 c2 = ((const float4*)(Wd + 256))[lane];
    float4 bb = ((const float4*)b1)[lane];
    float4 w2 = ((const float4*)W2)[lane];
    float b2v = b2[0];

    float wmax = -FLT_MAX;
    for (int e = gw; e < E; e += nw) {
        int sn = src[e], dn = dst[e];
        float dx = pos[dn * 3 + 0] - pos[sn * 3 + 0];
        float dy = pos[dn * 3 + 1] - pos[sn * 3 + 1];
        float dz = pos[dn * 3 + 2] - pos[sn * 3 + 2];

        float4 a  = ((const float4*)(g_u + (size_t)dn * 128))[lane];
        float4 bj = ((const float4*)(g_v + (size_t)sn * 128))[lane];

        float v0 = fmaxf(a.x + bj.x + bb.x + dx * c0.x + dy * c1.x + dz * c2.x, 0.f);
        float v1 = fmaxf(a.y + bj.y + bb.y + dx * c0.y + dy * c1.y + dz * c2.y, 0.f);
        float v2 = fmaxf(a.z + bj.z + bb.z + dx * c0.z + dy * c1.z + dz * c2.z, 0.f);
        float v3 = fmaxf(a.w + bj.w + bb.w + dx * c0.w + dy * c1.w + dz * c2.w, 0.f);
        float p = v0 * w2.x + v1 * w2.y + v2 * w2.z + v3 * w2.w;

        for (int o = 16; o; o >>= 1) p += __shfl_xor_sync(0xffffffffu, p, o);
        float s = p + b2v;
        if (lane == 0) g_s[e] = s;
        wmax = fmaxf(wmax, s);
    }

    __shared__ float wm[8];
    if (lane == 0) wm[wid] = wmax;
    __syncthreads();
    if (threadIdx.x == 0) {
        float m = wm[0];
        for (int i = 1; i < (int)(blockDim.x >> 5); i++) m = fmaxf(m, wm[i]);
        atomicMax(&g_maxkey, fkey(m));
    }
}

// ---------------------------------------------------------------------------
// Gather aggregation (atomic-free): one warp per node, register accumulate.
// aggr[node] = sum over incoming edges e: h[src[e]] * p[e]
// ---------------------------------------------------------------------------
__global__ void aggr_k(const int* __restrict__ src, int N) {
    int lane = threadIdx.x & 31;
    int node = (blockIdx.x * blockDim.x + threadIdx.x) >> 5;
    if (node >= N) return;
    int beg = node ? g_off[node - 1] : 0;
    int end = g_off[node];
    float4 acc = make_float4(0.f, 0.f, 0.f, 0.f);
    for (int i = beg; i < end; i++) {
        int e = g_eid[i];
        float c = g_s[e];
        int sn = src[e];
        float4 x = ((const float4*)(g_h + (size_t)sn * 128))[lane];
        acc.x += x.x * c; acc.y += x.y * c; acc.z += x.z * c; acc.w += x.w * c;
    }
    ((float4*)(g_aggr + (size_t)node * 128))[lane] = acc;
}

// ---------------------------------------------------------------------------
// Head (composed, K=64): out[row] = relu(R[row]@W1c + b1c) @ W2 + b2
// ---------------------------------------------------------------------------
__global__ void head_k(const float* __restrict__ R, const float* __restrict__ W1c,
                       const float* __restrict__ b1c, const float* __restrict__ W2,
                       const float* __restrict__ b2, float* __restrict__ out, int n) {
    __shared__ float W1s[64 * 64];
    __shared__ float b1s[64];
    __shared__ float W2s[64];
    __shared__ float rows[8][64];
    int t = threadIdx.x, lane = t & 31, wid = t >> 5;
    for (int i = t; i < 64 * 64; i += 256) W1s[i] = W1c[i];
    if (t < 64) { b1s[t] = b1c[t]; W2s[t] = W2[t]; }
    __syncthreads();
    float b2v = b2[0];
    for (int row = blockIdx.x * 8 + wid; row < n; row += gridDim.x * 8) {
        if (lane < 16) ((float4*)rows[wid])[lane] = ((const float4*)(R + (size_t)row * 64))[lane];
        __syncwarp();
        float h0 = b1s[lane], h1 = b1s[lane + 32];
#pragma unroll 8
        for (int k = 0; k < 64; k++) {
            float x = rows[wid][k];
            h0 += x * W1s[k * 64 + lane];
            h1 += x * W1s[k * 64 + lane + 32];
        }
        float p = fmaxf(h0, 0.f) * W2s[lane] + fmaxf(h1, 0.f) * W2s[lane + 32];
        for (int o = 16; o; o >>= 1) p += __shfl_xor_sync(0xffffffffu, p, o);
        if (lane == 0) out[row] = p + b2v;
        __syncwarp();
    }
}

// ---------------------------------------------------------------------------
extern "C" void kernel_launch(void* const* d_in, const int* in_sizes, int n_in,
                              void* d_out, int out_size) {
    const float* mol_x  = (const float*)d_in[0];
    const float* pos    = (const float*)d_in[1];
    const float* rx     = (const float*)d_in[2];
    const float* tx     = (const float*)d_in[3];
    const int*   ei     = (const int*)d_in[4];
    const float* W_node = (const float*)d_in[5];
    const float* b_node = (const float*)d_in[6];
    const float* W_att1 = (const float*)d_in[7];
    const float* b_att1 = (const float*)d_in[8];
    const float* W_att2 = (const float*)d_in[9];
    const float* b_att2 = (const float*)d_in[10];
    const float* W_upd  = (const float*)d_in[11];
    const float* b_upd  = (const float*)d_in[12];
    const float* Wy1 = (const float*)d_in[13];
    const float* by1 = (const float*)d_in[14];
    const float* Wy2 = (const float*)d_in[15];
    const float* by2 = (const float*)d_in[16];
    const float* Wa1 = (const float*)d_in[17];
    const float* ba1 = (const float*)d_in[18];
    const float* Wa2 = (const float*)d_in[19];
    const float* ba2 = (const float*)d_in[20];

    int N  = in_sizes[0] / 64;
    int NR = in_sizes[2] / 64;
    int NT = in_sizes[3] / 64;
    int E  = in_sizes[4] / 2;
    const int* srcP = ei;
    const int* dstP = ei + E;

    float* out   = (float*)d_out;
    float* out_y = out;             // pred_yield  [NR]
    float* out_a = out + NR;        // pred_activity [NT]
    float* out_m = out + NR + NT;   // mol_feats [N,128]

    float *hP, *agP, *sumP, *W1yP, *b1yP, *W1aP, *b1aP;
    cudaGetSymbolAddress((void**)&hP,   g_h);
    cudaGetSymbolAddress((void**)&agP,  g_aggr);
    cudaGetSymbolAddress((void**)&sumP, g_sum);
    cudaGetSymbolAddress((void**)&W1yP, g_W1y);
    cudaGetSymbolAddress((void**)&b1yP, g_b1y);
    cudaGetSymbolAddress((void**)&W1aP, g_W1a);
    cudaGetSymbolAddress((void**)&b1aP, g_b1a);

    int smem_enc  = (3 * 64 * 128 + 3 * 128 + 32 * 64) * 4;   // ~108 KB
    int smem_gemm = (128 * 128 + 32 * 128) * 4;               // 80 KB
    cudaFuncSetAttribute(enc_k,  cudaFuncAttributeMaxDynamicSharedMemorySize, smem_enc);
    cudaFuncSetAttribute(gemm_k, cudaFuncAttributeMaxDynamicSharedMemorySize, smem_gemm);

    auto pgrid = [](int rows, int cap) {
        int tiles = (rows + 31) / 32;
        return tiles < cap ? tiles : cap;
    };

    init_k<<<128, 256>>>(N);

    // composite weights
    compose_uv_k<<<65, 256>>>(W_node, b_node, W_att1);
    compose_head_k<<<17, 256>>>(W_node, b_node, Wy1, by1, W1yP, b1yP);
    compose_head_k<<<17, 256>>>(W_node, b_node, Wa1, ba1, W1aP, b1aP);

    // CSR histogram + scan (independent of encoder)
    hist_k<<<592, 256>>>(dstP, E);
    scan_k<<<1, 1024>>>(N);

    // fused encoder: h, u, v from mol_x
    enc_k<<<pgrid(N, 2 * 148), 128, smem_enc>>>(mol_x, W_node, b_node, N);

    // per-edge score + fused global max (persistent warps)
    edge_k<<<592, 256>>>(srcP, dstP, pos, W_att1 + 256 * 128, b_att1, W_att2, b_att2, E);

    // exp + sum + CSR fill
    fill_k<<<592, 256>>>(dstP, E);

    // atomic-free gather aggregation
    aggr_k<<<(N * 32 + 255) / 256, 256>>>(srcP, N);

    // update GEMM -> mol_feats, 1/sum folded into epilogue
    gemm_k<<<pgrid(N, 2 * 148), 128, smem_gemm>>>(agP, W_upd, b_upd, out_m, N, sumP);

    // heads straight from rx/tx via composed layer-1
    head_k<<<(NR + 7) / 8, 256>>>(rx, W1yP, b1yP, Wy2, by2, out_y, NR);
    head_k<<<(NT + 7) / 8, 256>>>(tx, W1aP, b1aP, Wa2, ba2, out_a, NT);
}

// round 6
// speedup vs baseline: 2.1200x; 2.1200x over previous
#include <cuda_runtime.h>
#include <math.h>
#include <float.h>

#define NMAX 50000
#define EMAX 400000

// Scratch (allocation-free rule: __device__ globals)
__device__ float g_u[NMAX * 128];
__device__ float g_v[NMAX * 128];
__device__ float g_aggr64[NMAX * 64];   // aggregated mol_x (64-wide)
__device__ float g_sp[NMAX];            // per-node sum of p
__device__ float g_s[EMAX];             // edge scores
__device__ unsigned int g_maxkey;
__device__ float g_sum;
// composite weights
__device__ float g_Wcu[64 * 128], g_Wcv[64 * 128], g_Wnu[64 * 128];
__device__ float g_bcu[128], g_bcv[128], g_bnu[128];
__device__ float g_W1y[64 * 64], g_b1y[64];
__device__ float g_W1a[64 * 64], g_b1a[64];

// --- monotonic float<->uint key for atomicMax over signed floats ---
__device__ __forceinline__ unsigned fkey(float f) {
    unsigned b = __float_as_uint(f);
    return (b & 0x80000000u) ? ~b : (b | 0x80000000u);
}
__device__ __forceinline__ float fdecode(unsigned k) {
    return __uint_as_float((k & 0x80000000u) ? (k ^ 0x80000000u) : ~k);
}

// ---------------------------------------------------------------------------
// init: zero aggr64 + sp, reset scalars
// ---------------------------------------------------------------------------
__global__ void init_k(int N) {
    int i = blockIdx.x * blockDim.x + threadIdx.x;
    if (i == 0) { g_maxkey = 0u; g_sum = 0.f; }
    int tot = N * 64;
    for (int j = i; j < tot; j += gridDim.x * blockDim.x) g_aggr64[j] = 0.f;
    for (int j = i; j < N; j += gridDim.x * blockDim.x) g_sp[j] = 0.f;
}

// ---------------------------------------------------------------------------
// ONE kernel for all composite weights (33280 outputs, K=128 dots):
//  Wcu = Wn@Wi, Wcv = Wn@Wj, Wnu = Wn@Wupd    (each [64,128])
//  W1y = Wn@Wy1, W1a = Wn@Wa1                  (each [64,64])
//  bcu = bn@Wi, bcv = bn@Wj, bnu = bn@Wupd, b1y = bn@Wy1+by1, b1a = bn@Wa1+ba1
// ---------------------------------------------------------------------------
__global__ void compose_all_k(const float* __restrict__ Wn, const float* __restrict__ bn,
                              const float* __restrict__ Watt, const float* __restrict__ Wupd,
                              const float* __restrict__ Wy1, const float* __restrict__ by1,
                              const float* __restrict__ Wa1, const float* __restrict__ ba1) {
    int id = blockIdx.x * blockDim.x + threadIdx.x;
    if (id < 24576) {                     // three [64,128] composites
        int sel = id >> 13, k = id & 8191, f = k >> 7, j = k & 127;
        const float* B = (sel == 0) ? Watt : (sel == 1) ? (Watt + 128 * 128) : Wupd;
        float* O = (sel == 0) ? g_Wcu : (sel == 1) ? g_Wcv : g_Wnu;
        float a = 0.f;
        for (int m = 0; m < 128; m++) a += Wn[f * 128 + m] * B[m * 128 + j];
        O[k] = a;
    } else if (id < 32768) {              // two [64,64] head composites
        int k = id - 24576, sel = k >> 12, kk = k & 4095, f = kk >> 6, j = kk & 63;
        const float* B = sel ? Wa1 : Wy1;
        float* O = sel ? g_W1a : g_W1y;
        float a = 0.f;
        for (int m = 0; m < 128; m++) a += Wn[f * 128 + m] * B[m * 64 + j];
        O[kk] = a;
    } else if (id < 33152) {              // three [128] bias composites
        int k = id - 32768, sel = k >> 7, j = k & 127;
        const float* B = (sel == 0) ? Watt : (sel == 1) ? (Watt + 128 * 128) : Wupd;
        float* O = (sel == 0) ? g_bcu : (sel == 1) ? g_bcv : g_bnu;
        float a = 0.f;
        for (int m = 0; m < 128; m++) a += bn[m] * B[m * 128 + j];
        O[j] = a;
    } else if (id < 33280) {              // two [64] head biases
        int k = id - 33152, sel = k >> 6, j = k & 63;
        const float* B = sel ? Wa1 : Wy1;
        float a = sel ? ba1[j] : by1[j];
        for (int m = 0; m < 128; m++) a += bn[m] * B[m * 64 + j];
        (sel ? g_b1a : g_b1y)[j] = a;
    }
}

// ---------------------------------------------------------------------------
// Encoder: u,v [n,128] from mol_x [n,64] via composite weights.
// 256 threads: col = t&127, row-half = t>>7; 32-row tiles; acc[16].
// smem ~74KB -> 2 blocks/SM -> 16 warps/SM.
// ---------------------------------------------------------------------------
__global__ void __launch_bounds__(256)
enc_k(const float* __restrict__ X, int n) {
    extern __shared__ float sm[];
    float* Ws = sm;            // 2 * 8192
    float* bs = sm + 16384;    // 2 * 128
    float* Xs = bs + 256;      // 32 * 64
    int t = threadIdx.x;
    int col = t & 127, half = t >> 7;
    for (int i = t; i < 2048; i += 256) ((float4*)Ws)[i]          = ((const float4*)g_Wcu)[i];
    for (int i = t; i < 2048; i += 256) ((float4*)(Ws + 8192))[i] = ((const float4*)g_Wcv)[i];
    if (t < 128) { bs[t] = g_bcu[t]; bs[128 + t] = g_bcv[t]; }

    for (int row0 = blockIdx.x * 32; row0 < n; row0 += gridDim.x * 32) {
        int nr = min(32, n - row0);
        __syncthreads();
        for (int i = t; i < nr * 16; i += 256)
            ((float4*)Xs)[i] = ((const float4*)(X + (size_t)row0 * 64))[i];
        __syncthreads();

#pragma unroll 1
        for (int g = 0; g < 2; g++) {
            const float* Wg = Ws + g * 8192;
            float acc[16];
#pragma unroll
            for (int r = 0; r < 16; r++) acc[r] = 0.f;
            for (int k4 = 0; k4 < 64; k4 += 4) {
                float w0 = Wg[(k4 + 0) * 128 + col];
                float w1 = Wg[(k4 + 1) * 128 + col];
                float w2 = Wg[(k4 + 2) * 128 + col];
                float w3 = Wg[(k4 + 3) * 128 + col];
#pragma unroll
                for (int r = 0; r < 16; r++) {
                    float4 xv = *(const float4*)&Xs[(half * 16 + r) * 64 + k4];
                    acc[r] += xv.x * w0 + xv.y * w1 + xv.z * w2 + xv.w * w3;
                }
            }
            float bv = bs[g * 128 + col];
            float* O = g ? g_v : g_u;
            int rmax = min(16, nr - half * 16);
            for (int r = 0; r < rmax; r++)
                O[(size_t)(row0 + half * 16 + r) * 128 + col] = acc[r] + bv;
        }
    }
}

// ---------------------------------------------------------------------------
// Edge attention score + fused global max. Persistent warps; weights in regs.
// ---------------------------------------------------------------------------
__global__ void edge_k(const int* __restrict__ src, const int* __restrict__ dst,
                       const float* __restrict__ pos,
                       const float* __restrict__ Wd, const float* __restrict__ b1,
                       const float* __restrict__ W2, const float* __restrict__ b2,
                       int E) {
    int lane = threadIdx.x & 31;
    int wid = threadIdx.x >> 5;
    int gw = (blockIdx.x * blockDim.x + threadIdx.x) >> 5;
    int nw = (gridDim.x * blockDim.x) >> 5;

    float4 c0 = ((const float4*)Wd)[lane];
    float4 c1 = ((const float4*)(Wd + 128))[lane];
    float4 c2 = ((const float4*)(Wd + 256))[lane];
    float4 bb = ((const float4*)b1)[lane];
    float4 w2 = ((const float4*)W2)[lane];
    float b2v = b2[0];

    float wmax = -FLT_MAX;
    for (int e = gw; e < E; e += nw) {
        int sn = src[e], dn = dst[e];
        float dx = pos[dn * 3 + 0] - pos[sn * 3 + 0];
        float dy = pos[dn * 3 + 1] - pos[sn * 3 + 1];
        float dz = pos[dn * 3 + 2] - pos[sn * 3 + 2];

        float4 a  = ((const float4*)(g_u + (size_t)dn * 128))[lane];
        float4 bj = ((const float4*)(g_v + (size_t)sn * 128))[lane];

        float v0 = fmaxf(a.x + bj.x + bb.x + dx * c0.x + dy * c1.x + dz * c2.x, 0.f);
        float v1 = fmaxf(a.y + bj.y + bb.y + dx * c0.y + dy * c1.y + dz * c2.y, 0.f);
        float v2 = fmaxf(a.z + bj.z + bb.z + dx * c0.z + dy * c1.z + dz * c2.z, 0.f);
        float v3 = fmaxf(a.w + bj.w + bb.w + dx * c0.w + dy * c1.w + dz * c2.w, 0.f);
        float p = v0 * w2.x + v1 * w2.y + v2 * w2.z + v3 * w2.w;

        for (int o = 16; o; o >>= 1) p += __shfl_xor_sync(0xffffffffu, p, o);
        float s = p + b2v;
        if (lane == 0) g_s[e] = s;
        wmax = fmaxf(wmax, s);
    }

    __shared__ float wm[8];
    if (lane == 0) wm[wid] = wmax;
    __syncthreads();
    if (threadIdx.x == 0) {
        float m = wm[0];
        for (int i = 1; i < (int)(blockDim.x >> 5); i++) m = fmaxf(m, wm[i]);
        atomicMax(&g_maxkey, fkey(m));
    }
}

// ---------------------------------------------------------------------------
// Fused exp + sum + 64-wide scatter. HALF-WARP (16 lanes) per edge.
// aggr64[dst] += mol_x[src] * p ; sp[dst] += p ; g_sum += p.
// ---------------------------------------------------------------------------
__global__ void scatter_k(const int* __restrict__ src, const int* __restrict__ dst,
                          const float* __restrict__ molx, int E) {
    int tid = blockIdx.x * blockDim.x + threadIdx.x;
    int hw = tid >> 4;          // half-warp id = edge id
    int l16 = threadIdx.x & 15;

    float mx = fdecode(g_maxkey);
    float loc = 0.f;
    if (hw < E) {
        float p = expf(g_s[hw] - mx);
        int sn = src[hw], dn = dst[hw];
        float4 x = ((const float4*)(molx + (size_t)sn * 64))[l16];
        float* basep = g_aggr64 + (size_t)dn * 64 + l16 * 4;
        asm volatile("red.global.add.v4.f32 [%0], {%1, %2, %3, %4};"
                     :: "l"(basep), "f"(x.x * p), "f"(x.y * p), "f"(x.z * p), "f"(x.w * p)
                     : "memory");
        if (l16 == 0) {
            atomicAdd(&g_sp[dn], p);
            loc = p;
        }
    }
    // block-reduce loc -> g_sum
    for (int o = 16; o; o >>= 1) loc += __shfl_xor_sync(0xffffffffu, loc, o);
    __shared__ float ws[8];
    int lane = threadIdx.x & 31, wid = threadIdx.x >> 5;
    if (lane == 0) ws[wid] = loc;
    __syncthreads();
    if (threadIdx.x == 0) {
        float tot = 0.f;
        for (int i = 0; i < (int)(blockDim.x >> 5); i++) tot += ws[i];
        atomicAdd(&g_sum, tot);
    }
}

// ---------------------------------------------------------------------------
// Final GEMM (K=64): mol_feats = (aggr64@Wnu + sp*bnu)/sum + b_upd
// 256 threads: col = t&127, half = t>>7; 32-row tiles; acc[16]. smem 40KB.
// ---------------------------------------------------------------------------
__global__ void __launch_bounds__(256)
final_k(const float* __restrict__ bupd, float* __restrict__ Y, int n) {
    extern __shared__ float sm[];
    float* Ws = sm;            // 8192
    float* bs = sm + 8192;     // 2*128 (bnu, bupd)
    float* Xs = bs + 256;      // 32*64
    int t = threadIdx.x;
    int col = t & 127, half = t >> 7;
    for (int i = t; i < 2048; i += 256) ((float4*)Ws)[i] = ((const float4*)g_Wnu)[i];
    if (t < 128) { bs[t] = g_bnu[t]; bs[128 + t] = bupd[t]; }

    float is = 1.f / g_sum;

    for (int row0 = blockIdx.x * 32; row0 < n; row0 += gridDim.x * 32) {
        int nr = min(32, n - row0);
        __syncthreads();
        for (int i = t; i < nr * 16; i += 256)
            ((float4*)Xs)[i] = ((const float4*)(g_aggr64 + (size_t)row0 * 64))[i];
        __syncthreads();

        float acc[16];
#pragma unroll
        for (int r = 0; r < 16; r++) acc[r] = 0.f;
        for (int k4 = 0; k4 < 64; k4 += 4) {
            float w0 = Ws[(k4 + 0) * 128 + col];
            float w1 = Ws[(k4 + 1) * 128 + col];
            float w2 = Ws[(k4 + 2) * 128 + col];
            float w3 = Ws[(k4 + 3) * 128 + col];
#pragma unroll
            for (int r = 0; r < 16; r++) {
                float4 xv = *(const float4*)&Xs[(half * 16 + r) * 64 + k4];
                acc[r] += xv.x * w0 + xv.y * w1 + xv.z * w2 + xv.w * w3;
            }
        }
        float bnuv = bs[col], bupv = bs[128 + col];
        int rmax = min(16, nr - half * 16);
        for (int r = 0; r < rmax; r++) {
            int row = row0 + half * 16 + r;
            float sp = g_sp[row];
            Y[(size_t)row * 128 + col] = (acc[r] + sp * bnuv) * is + bupv;
        }
    }
}

// ---------------------------------------------------------------------------
// Head (composed, K=64): out[row] = relu(R[row]@W1c + b1c) @ W2 + b2
// ---------------------------------------------------------------------------
__global__ void head_k(const float* __restrict__ R, const float* __restrict__ W1c,
                       const float* __restrict__ b1c, const float* __restrict__ W2,
                       const float* __restrict__ b2, float* __restrict__ out, int n) {
    __shared__ float W1s[64 * 64];
    __shared__ float b1s[64];
    __shared__ float W2s[64];
    __shared__ float rows[8][64];
    int t = threadIdx.x, lane = t & 31, wid = t >> 5;
    for (int i = t; i < 64 * 64; i += 256) W1s[i] = W1c[i];
    if (t < 64) { b1s[t] = b1c[t]; W2s[t] = W2[t]; }
    __syncthreads();
    float b2v = b2[0];
    for (int row = blockIdx.x * 8 + wid; row < n; row += gridDim.x * 8) {
        if (lane < 16) ((float4*)rows[wid])[lane] = ((const float4*)(R + (size_t)row * 64))[lane];
        __syncwarp();
        float h0 = b1s[lane], h1 = b1s[lane + 32];
#pragma unroll 8
        for (int k = 0; k < 64; k++) {
            float x = rows[wid][k];
            h0 += x * W1s[k * 64 + lane];
            h1 += x * W1s[k * 64 + lane + 32];
        }
        float p = fmaxf(h0, 0.f) * W2s[lane] + fmaxf(h1, 0.f) * W2s[lane + 32];
        for (int o = 16; o; o >>= 1) p += __shfl_xor_sync(0xffffffffu, p, o);
        if (lane == 0) out[row] = p + b2v;
        __syncwarp();
    }
}

// ---------------------------------------------------------------------------
extern "C" void kernel_launch(void* const* d_in, const int* in_sizes, int n_in,
                              void* d_out, int out_size) {
    const float* mol_x  = (const float*)d_in[0];
    const float* pos    = (const float*)d_in[1];
    const float* rx     = (const float*)d_in[2];
    const float* tx     = (const float*)d_in[3];
    const int*   ei     = (const int*)d_in[4];
    const float* W_node = (const float*)d_in[5];
    const float* b_node = (const float*)d_in[6];
    const float* W_att1 = (const float*)d_in[7];
    const float* b_att1 = (const float*)d_in[8];
    const float* W_att2 = (const float*)d_in[9];
    const float* b_att2 = (const float*)d_in[10];
    const float* W_upd  = (const float*)d_in[11];
    const float* b_upd  = (const float*)d_in[12];
    const float* Wy1 = (const float*)d_in[13];
    const float* by1 = (const float*)d_in[14];
    const float* Wy2 = (const float*)d_in[15];
    const float* by2 = (const float*)d_in[16];
    const float* Wa1 = (const float*)d_in[17];
    const float* ba1 = (const float*)d_in[18];
    const float* Wa2 = (const float*)d_in[19];
    const float* ba2 = (const float*)d_in[20];

    int N  = in_sizes[0] / 64;
    int NR = in_sizes[2] / 64;
    int NT = in_sizes[3] / 64;
    int E  = in_sizes[4] / 2;
    const int* srcP = ei;
    const int* dstP = ei + E;

    float* out   = (float*)d_out;
    float* out_y = out;             // pred_yield  [NR]
    float* out_a = out + NR;        // pred_activity [NT]
    float* out_m = out + NR + NT;   // mol_feats [N,128]

    float *W1yP, *b1yP, *W1aP, *b1aP;
    cudaGetSymbolAddress((void**)&W1yP, g_W1y);
    cudaGetSymbolAddress((void**)&b1yP, g_b1y);
    cudaGetSymbolAddress((void**)&W1aP, g_W1a);
    cudaGetSymbolAddress((void**)&b1aP, g_b1a);

    int smem_enc   = (2 * 64 * 128 + 2 * 128 + 32 * 64) * 4;  // ~74 KB
    int smem_final = (64 * 128 + 2 * 128 + 32 * 64) * 4;      // ~42 KB
    cudaFuncSetAttribute(enc_k,   cudaFuncAttributeMaxDynamicSharedMemorySize, smem_enc);
    cudaFuncSetAttribute(final_k, cudaFuncAttributeMaxDynamicSharedMemorySize, smem_final);

    auto pgrid = [](int rows, int cap) {
        int tiles = (rows + 31) / 32;
        return tiles < cap ? tiles : cap;
    };

    init_k<<<256, 256>>>(N);
    compose_all_k<<<130, 256>>>(W_node, b_node, W_att1, W_upd, Wy1, by1, Wa1, ba1);

    // u, v from mol_x via composite weights
    enc_k<<<pgrid(N, 2 * 148), 256, smem_enc>>>(mol_x, N);

    // per-edge score + fused global max (persistent warps)
    edge_k<<<592, 256>>>(srcP, dstP, pos, W_att1 + 256 * 128, b_att1, W_att2, b_att2, E);

    // exp + sum + 64-wide scatter (half-warp per edge)
    scatter_k<<<(E * 16 + 255) / 256, 256>>>(srcP, dstP, mol_x, E);

    // final K=64 GEMM -> mol_feats
    final_k<<<pgrid(N, 4 * 148), 256, smem_final>>>(b_upd, out_m, N);

    // heads straight from rx/tx via composed layer-1
    head_k<<<(NR + 7) / 8, 256>>>(rx, W1yP, b1yP, Wy2, by2, out_y, NR);
    head_k<<<(NT + 7) / 8, 256>>>(tx, W1aP, b1aP, Wa2, ba2, out_a, NT);
}

// round 9
// speedup vs baseline: 2.4415x; 1.1517x over previous
#include <cuda_runtime.h>
#include <math.h>
#include <float.h>

#define NMAX 50000
#define EMAX 400000

// Scratch (allocation-free rule: __device__ globals)
__device__ float g_u[NMAX * 128];
__device__ float g_v[NMAX * 128];
__device__ float g_aggr64[NMAX * 64];   // aggregated mol_x (64-wide)
__device__ float g_sp[NMAX];            // per-node sum of p
__device__ float g_s[EMAX];             // edge scores
__device__ unsigned int g_maxkey;
__device__ float g_sum;
// composite weights
__device__ float g_Wcu[64 * 128], g_Wcv[64 * 128], g_Wnu[64 * 128];
__device__ float g_bcu[128], g_bcv[128], g_bnu[128];
__device__ float g_W1y[64 * 64], g_b1y[64];
__device__ float g_W1a[64 * 64], g_b1a[64];

// --- monotonic float<->uint key for atomicMax over signed floats ---
__device__ __forceinline__ unsigned fkey(float f) {
    unsigned b = __float_as_uint(f);
    return (b & 0x80000000u) ? ~b : (b | 0x80000000u);
}
__device__ __forceinline__ float fdecode(unsigned k) {
    return __uint_as_float((k & 0x80000000u) ? (k ^ 0x80000000u) : ~k);
}

// ---------------------------------------------------------------------------
__global__ void init_k(int N) {
    int i = blockIdx.x * blockDim.x + threadIdx.x;
    if (i == 0) { g_maxkey = 0u; g_sum = 0.f; }
    int tot = N * 64;
    for (int j = i; j < tot; j += gridDim.x * blockDim.x) g_aggr64[j] = 0.f;
    for (int j = i; j < N; j += gridDim.x * blockDim.x) g_sp[j] = 0.f;
}

// ---------------------------------------------------------------------------
// ONE kernel for all composite weights (33280 outputs, K=128 dots)
// ---------------------------------------------------------------------------
__global__ void compose_all_k(const float* __restrict__ Wn, const float* __restrict__ bn,
                              const float* __restrict__ Watt, const float* __restrict__ Wupd,
                              const float* __restrict__ Wy1, const float* __restrict__ by1,
                              const float* __restrict__ Wa1, const float* __restrict__ ba1) {
    int id = blockIdx.x * blockDim.x + threadIdx.x;
    if (id < 24576) {                     // three [64,128] composites
        int sel = id >> 13, k = id & 8191, f = k >> 7, j = k & 127;
        const float* B = (sel == 0) ? Watt : (sel == 1) ? (Watt + 128 * 128) : Wupd;
        float* O = (sel == 0) ? g_Wcu : (sel == 1) ? g_Wcv : g_Wnu;
        float a = 0.f;
        for (int m = 0; m < 128; m++) a += Wn[f * 128 + m] * B[m * 128 + j];
        O[k] = a;
    } else if (id < 32768) {              // two [64,64] head composites
        int k = id - 24576, sel = k >> 12, kk = k & 4095, f = kk >> 6, j = kk & 63;
        const float* B = sel ? Wa1 : Wy1;
        float* O = sel ? g_W1a : g_W1y;
        float a = 0.f;
        for (int m = 0; m < 128; m++) a += Wn[f * 128 + m] * B[m * 64 + j];
        O[kk] = a;
    } else if (id < 33152) {              // three [128] bias composites
        int k = id - 32768, sel = k >> 7, j = k & 127;
        const float* B = (sel == 0) ? Watt : (sel == 1) ? (Watt + 128 * 128) : Wupd;
        float* O = (sel == 0) ? g_bcu : (sel == 1) ? g_bcv : g_bnu;
        float a = 0.f;
        for (int m = 0; m < 128; m++) a += bn[m] * B[m * 128 + j];
        O[j] = a;
    } else if (id < 33280) {              // two [64] head biases
        int k = id - 33152, sel = k >> 6, j = k & 63;
        const float* B = sel ? Wa1 : Wy1;
        float a = sel ? ba1[j] : by1[j];
        for (int m = 0; m < 128; m++) a += bn[m] * B[m * 64 + j];
        (sel ? g_b1a : g_b1y)[j] = a;
    }
}

// ---------------------------------------------------------------------------
// Encoder: u,v [n,128] from mol_x [n,64] via composite weights.
// 256 threads: col = t&127, row-half = t>>7; 32-row tiles; acc[16].
// ---------------------------------------------------------------------------
__global__ void __launch_bounds__(256)
enc_k(const float* __restrict__ X, int n) {
    extern __shared__ float sm[];
    float* Ws = sm;            // 2 * 8192
    float* bs = sm + 16384;    // 2 * 128
    float* Xs = bs + 256;      // 32 * 64
    int t = threadIdx.x;
    int col = t & 127, half = t >> 7;
    for (int i = t; i < 2048; i += 256) ((float4*)Ws)[i]          = ((const float4*)g_Wcu)[i];
    for (int i = t; i < 2048; i += 256) ((float4*)(Ws + 8192))[i] = ((const float4*)g_Wcv)[i];
    if (t < 128) { bs[t] = g_bcu[t]; bs[128 + t] = g_bcv[t]; }

    for (int row0 = blockIdx.x * 32; row0 < n; row0 += gridDim.x * 32) {
        int nr = min(32, n - row0);
        __syncthreads();
        for (int i = t; i < nr * 16; i += 256)
            ((float4*)Xs)[i] = ((const float4*)(X + (size_t)row0 * 64))[i];
        __syncthreads();

#pragma unroll 1
        for (int g = 0; g < 2; g++) {
            const float* Wg = Ws + g * 8192;
            float acc[16];
#pragma unroll
            for (int r = 0; r < 16; r++) acc[r] = 0.f;
            for (int k4 = 0; k4 < 64; k4 += 4) {
                float w0 = Wg[(k4 + 0) * 128 + col];
                float w1 = Wg[(k4 + 1) * 128 + col];
                float w2 = Wg[(k4 + 2) * 128 + col];
                float w3 = Wg[(k4 + 3) * 128 + col];
#pragma unroll
                for (int r = 0; r < 16; r++) {
                    float4 xv = *(const float4*)&Xs[(half * 16 + r) * 64 + k4];
                    acc[r] += xv.x * w0 + xv.y * w1 + xv.z * w2 + xv.w * w3;
                }
            }
            float bv = bs[g * 128 + col];
            float* O = g ? g_v : g_u;
            int rmax = min(16, nr - half * 16);
            for (int r = 0; r < rmax; r++)
                O[(size_t)(row0 + half * 16 + r) * 128 + col] = acc[r] + bv;
        }
    }
}

// ---------------------------------------------------------------------------
// Edge attention score + fused global max. Persistent warps, TWO edges per
// iteration: both gathers issued up front, compute + shfl chains interleaved.
// ---------------------------------------------------------------------------
__global__ void edge_k(const int* __restrict__ src, const int* __restrict__ dst,
                       const float* __restrict__ pos,
                       const float* __restrict__ Wd, const float* __restrict__ b1,
                       const float* __restrict__ W2, const float* __restrict__ b2,
                       int E) {
    int lane = threadIdx.x & 31;
    int wid = threadIdx.x >> 5;
    int gw = (blockIdx.x * blockDim.x + threadIdx.x) >> 5;
    int nw = (gridDim.x * blockDim.x) >> 5;

    float4 c0 = ((const float4*)Wd)[lane];
    float4 c1 = ((const float4*)(Wd + 128))[lane];
    float4 c2 = ((const float4*)(Wd + 256))[lane];
    float4 bb = ((const float4*)b1)[lane];
    float4 w2 = ((const float4*)W2)[lane];
    float b2v = b2[0];

    float wmax = -FLT_MAX;
    for (int e0 = gw * 2; e0 < E; e0 += 2 * nw) {
        int e1 = e0 + 1;
        bool has1 = e1 < E;                 // warp-uniform
        int e1c = has1 ? e1 : e0;           // clamped index (always valid)

        int sn0 = src[e0], dn0 = dst[e0];
        int sn1 = src[e1c], dn1 = dst[e1c];

        // issue all gathers first (maximize MLP)
        float4 a0 = ((const float4*)(g_u + (size_t)dn0 * 128))[lane];
        float4 j0 = ((const float4*)(g_v + (size_t)sn0 * 128))[lane];
        float4 a1 = ((const float4*)(g_u + (size_t)dn1 * 128))[lane];
        float4 j1 = ((const float4*)(g_v + (size_t)sn1 * 128))[lane];

        float dx0 = pos[dn0 * 3 + 0] - pos[sn0 * 3 + 0];
        float dy0 = pos[dn0 * 3 + 1] - pos[sn0 * 3 + 1];
        float dz0 = pos[dn0 * 3 + 2] - pos[sn0 * 3 + 2];
        float dx1 = pos[dn1 * 3 + 0] - pos[sn1 * 3 + 0];
        float dy1 = pos[dn1 * 3 + 1] - pos[sn1 * 3 + 1];
        float dz1 = pos[dn1 * 3 + 2] - pos[sn1 * 3 + 2];

        float p0, p1;
        {
            float t0 = fmaxf(a0.x + j0.x + bb.x + dx0 * c0.x + dy0 * c1.x + dz0 * c2.x, 0.f);
            float t1 = fmaxf(a0.y + j0.y + bb.y + dx0 * c0.y + dy0 * c1.y + dz0 * c2.y, 0.f);
            float t2 = fmaxf(a0.z + j0.z + bb.z + dx0 * c0.z + dy0 * c1.z + dz0 * c2.z, 0.f);
            float t3 = fmaxf(a0.w + j0.w + bb.w + dx0 * c0.w + dy0 * c1.w + dz0 * c2.w, 0.f);
            p0 = t0 * w2.x + t1 * w2.y + t2 * w2.z + t3 * w2.w;
        }
        {
            float t0 = fmaxf(a1.x + j1.x + bb.x + dx1 * c0.x + dy1 * c1.x + dz1 * c2.x, 0.f);
            float t1 = fmaxf(a1.y + j1.y + bb.y + dx1 * c0.y + dy1 * c1.y + dz1 * c2.y, 0.f);
            float t2 = fmaxf(a1.z + j1.z + bb.z + dx1 * c0.z + dy1 * c1.z + dz1 * c2.z, 0.f);
            float t3 = fmaxf(a1.w + j1.w + bb.w + dx1 * c0.w + dy1 * c1.w + dz1 * c2.w, 0.f);
            p1 = t0 * w2.x + t1 * w2.y + t2 * w2.z + t3 * w2.w;
        }

        // interleaved independent shuffle chains
#pragma unroll
        for (int o = 16; o; o >>= 1) {
            p0 += __shfl_xor_sync(0xffffffffu, p0, o);
            p1 += __shfl_xor_sync(0xffffffffu, p1, o);
        }
        float s0 = p0 + b2v;
        float s1 = p1 + b2v;
        if (lane == 0) g_s[e0] = s0;
        wmax = fmaxf(wmax, s0);
        if (has1) {
            if (lane == 0) g_s[e1] = s1;
            wmax = fmaxf(wmax, s1);
        }
    }

    __shared__ float wm[8];
    if (lane == 0) wm[wid] = wmax;
    __syncthreads();
    if (threadIdx.x == 0) {
        float m = wm[0];
        for (int i = 1; i < (int)(blockDim.x >> 5); i++) m = fmaxf(m, wm[i]);
        atomicMax(&g_maxkey, fkey(m));
    }
}

// ---------------------------------------------------------------------------
// Fused exp + sum + 64-wide scatter. HALF-WARP (16 lanes) per edge.
// ---------------------------------------------------------------------------
__global__ void scatter_k(const int* __restrict__ src, const int* __restrict__ dst,
                          const float* __restrict__ molx, int E) {
    int tid = blockIdx.x * blockDim.x + threadIdx.x;
    int hw = tid >> 4;          // half-warp id = edge id
    int l16 = threadIdx.x & 15;

    float mx = fdecode(g_maxkey);
    float loc = 0.f;
    if (hw < E) {
        float p = expf(g_s[hw] - mx);
        int sn = src[hw], dn = dst[hw];
        float4 x = ((const float4*)(molx + (size_t)sn * 64))[l16];
        float* basep = g_aggr64 + (size_t)dn * 64 + l16 * 4;
        asm volatile("red.global.add.v4.f32 [%0], {%1, %2, %3, %4};"
                     :: "l"(basep), "f"(x.x * p), "f"(x.y * p), "f"(x.z * p), "f"(x.w * p)
                     : "memory");
        if (l16 == 0) {
            atomicAdd(&g_sp[dn], p);
            loc = p;
        }
    }
    for (int o = 16; o; o >>= 1) loc += __shfl_xor_sync(0xffffffffu, loc, o);
    __shared__ float ws[8];
    int lane = threadIdx.x & 31, wid = threadIdx.x >> 5;
    if (lane == 0) ws[wid] = loc;
    __syncthreads();
    if (threadIdx.x == 0) {
        float tot = 0.f;
        for (int i = 0; i < (int)(blockDim.x >> 5); i++) tot += ws[i];
        atomicAdd(&g_sum, tot);
    }
}

// ---------------------------------------------------------------------------
// Final GEMM (K=64): mol_feats = (aggr64@Wnu + sp*bnu)/sum + b_upd
// ---------------------------------------------------------------------------
__global__ void __launch_bounds__(256)
final_k(const float* __restrict__ bupd, float* __restrict__ Y, int n) {
    extern __shared__ float sm[];
    float* Ws = sm;            // 8192
    float* bs = sm + 8192;     // 2*128 (bnu, bupd)
    float* Xs = bs + 256;      // 32*64
    int t = threadIdx.x;
    int col = t & 127, half = t >> 7;
    for (int i = t; i < 2048; i += 256) ((float4*)Ws)[i] = ((const float4*)g_Wnu)[i];
    if (t < 128) { bs[t] = g_bnu[t]; bs[128 + t] = bupd[t]; }

    float is = 1.f / g_sum;

    for (int row0 = blockIdx.x * 32; row0 < n; row0 += gridDim.x * 32) {
        int nr = min(32, n - row0);
        __syncthreads();
        for (int i = t; i < nr * 16; i += 256)
            ((float4*)Xs)[i] = ((const float4*)(g_aggr64 + (size_t)row0 * 64))[i];
        __syncthreads();

        float acc[16];
#pragma unroll
        for (int r = 0; r < 16; r++) acc[r] = 0.f;
        for (int k4 = 0; k4 < 64; k4 += 4) {
            float w0 = Ws[(k4 + 0) * 128 + col];
            float w1 = Ws[(k4 + 1) * 128 + col];
            float w2 = Ws[(k4 + 2) * 128 + col];
            float w3 = Ws[(k4 + 3) * 128 + col];
#pragma unroll
            for (int r = 0; r < 16; r++) {
                float4 xv = *(const float4*)&Xs[(half * 16 + r) * 64 + k4];
                acc[r] += xv.x * w0 + xv.y * w1 + xv.z * w2 + xv.w * w3;
            }
        }
        float bnuv = bs[col], bupv = bs[128 + col];
        int rmax = min(16, nr - half * 16);
        for (int r = 0; r < rmax; r++) {
            int row = row0 + half * 16 + r;
            float sp = g_sp[row];
            Y[(size_t)row * 128 + col] = (acc[r] + sp * bnuv) * is + bupv;
        }
    }
}

// ---------------------------------------------------------------------------
// BOTH heads in one launch. Block picks (y) or (a) params by blockIdx.
// out[row] = relu(R[row]@W1c + b1c) @ W2 + b2
// ---------------------------------------------------------------------------
__global__ void heads_k(const float* __restrict__ Ry, const float* __restrict__ W2y,
                        const float* __restrict__ b2y, float* __restrict__ outY, int nY,
                        const float* __restrict__ Ra, const float* __restrict__ W2a,
                        const float* __restrict__ b2a, float* __restrict__ outA, int nA,
                        int blocksY) {
    __shared__ float W1s[64 * 64];
    __shared__ float b1s[64];
    __shared__ float W2s[64];
    __shared__ float rows[8][64];
    int t = threadIdx.x, lane = t & 31, wid = t >> 5;

    bool isY = blockIdx.x < blocksY;
    int bid = isY ? blockIdx.x : blockIdx.x - blocksY;
    const float* R   = isY ? Ry : Ra;
    const float* W1c = isY ? g_W1y : g_W1a;
    const float* b1c = isY ? g_b1y : g_b1a;
    const float* W2  = isY ? W2y : W2a;
    const float* b2  = isY ? b2y : b2a;
    float* out = isY ? outY : outA;
    int n = isY ? nY : nA;

    for (int i = t; i < 64 * 64; i += 256) W1s[i] = W1c[i];
    if (t < 64) { b1s[t] = b1c[t]; W2s[t] = W2[t]; }
    __syncthreads();
    float b2v = b2[0];
    int row = bid * 8 + wid;
    if (row < n) {
        if (lane < 16) ((float4*)rows[wid])[lane] = ((const float4*)(R + (size_t)row * 64))[lane];
        __syncwarp();
        float h0 = b1s[lane], h1 = b1s[lane + 32];
#pragma unroll 8
        for (int k = 0; k < 64; k++) {
            float x = rows[wid][k];
            h0 += x * W1s[k * 64 + lane];
            h1 += x * W1s[k * 64 + lane + 32];
        }
        float p = fmaxf(h0, 0.f) * W2s[lane] + fmaxf(h1, 0.f) * W2s[lane + 32];
        for (int o = 16; o; o >>= 1) p += __shfl_xor_sync(0xffffffffu, p, o);
        if (lane == 0) out[row] = p + b2v;
    }
}

// ---------------------------------------------------------------------------
extern "C" void kernel_launch(void* const* d_in, const int* in_sizes, int n_in,
                              void* d_out, int out_size) {
    const float* mol_x  = (const float*)d_in[0];
    const float* pos    = (const float*)d_in[1];
    const float* rx     = (const float*)d_in[2];
    const float* tx     = (const float*)d_in[3];
    const int*   ei     = (const int*)d_in[4];
    const float* W_node = (const float*)d_in[5];
    const float* b_node = (const float*)d_in[6];
    const float* W_att1 = (const float*)d_in[7];
    const float* b_att1 = (const float*)d_in[8];
    const float* W_att2 = (const float*)d_in[9];
    const float* b_att2 = (const float*)d_in[10];
    const float* W_upd  = (const float*)d_in[11];
    const float* b_upd  = (const float*)d_in[12];
    const float* Wy1 = (const float*)d_in[13];
    const float* by1 = (const float*)d_in[14];
    const float* Wy2 = (const float*)d_in[15];
    const float* by2 = (const float*)d_in[16];
    const float* Wa1 = (const float*)d_in[17];
    const float* ba1 = (const float*)d_in[18];
    const float* Wa2 = (const float*)d_in[19];
    const float* ba2 = (const float*)d_in[20];

    int N  = in_sizes[0] / 64;
    int NR = in_sizes[2] / 64;
    int NT = in_sizes[3] / 64;
    int E  = in_sizes[4] / 2;
    const int* srcP = ei;
    const int* dstP = ei + E;

    float* out   = (float*)d_out;
    float* out_y = out;             // pred_yield  [NR]
    float* out_a = out + NR;        // pred_activity [NT]
    float* out_m = out + NR + NT;   // mol_feats [N,128]

    int smem_enc   = (2 * 64 * 128 + 2 * 128 + 32 * 64) * 4;  // ~74 KB
    int smem_final = (64 * 128 + 2 * 128 + 32 * 64) * 4;      // ~42 KB
    cudaFuncSetAttribute(enc_k,   cudaFuncAttributeMaxDynamicSharedMemorySize, smem_enc);
    cudaFuncSetAttribute(final_k, cudaFuncAttributeMaxDynamicSharedMemorySize, smem_final);

    auto pgrid = [](int rows, int cap) {
        int tiles = (rows + 31) / 32;
        return tiles < cap ? tiles : cap;
    };

    init_k<<<256, 256>>>(N);
    compose_all_k<<<130, 256>>>(W_node, b_node, W_att1, W_upd, Wy1, by1, Wa1, ba1);

    // u, v from mol_x via composite weights
    enc_k<<<pgrid(N, 2 * 148), 256, smem_enc>>>(mol_x, N);

    // per-edge score + fused global max (persistent warps, 2-edge ILP)
    edge_k<<<592, 256>>>(srcP, dstP, pos, W_att1 + 256 * 128, b_att1, W_att2, b_att2, E);

    // exp + sum + 64-wide scatter (half-warp per edge)
    scatter_k<<<(E * 16 + 255) / 256, 256>>>(srcP, dstP, mol_x, E);

    // final K=64 GEMM -> mol_feats
    final_k<<<pgrid(N, 4 * 148), 256, smem_final>>>(b_upd, out_m, N);

    // both heads in one launch
    int blocksY = (NR + 7) / 8, blocksA = (NT + 7) / 8;
    heads_k<<<blocksY + blocksA, 256>>>(rx, Wy2, by2, out_y, NR,
                                        tx, Wa2, ba2, out_a, NT, blocksY);
}

// round 11
// speedup vs baseline: 2.4634x; 1.0090x over previous
#include <cuda_runtime.h>
#include <math.h>
#include <float.h>

#define NMAX 50000
#define EMAX 400000

// Scratch (allocation-free rule: __device__ globals)
__device__ float g_u[NMAX * 128];
__device__ float g_v[NMAX * 128];
__device__ float g_aggr64[NMAX * 64];   // aggregated mol_x (64-wide)
__device__ float g_sp[NMAX];            // per-node sum of p
__device__ float g_s[EMAX];             // edge scores
__device__ unsigned int g_maxkey;
__device__ float g_sum;
// composite weights
__device__ float g_Wcu[64 * 128], g_Wcv[64 * 128], g_Wnu[64 * 128];
__device__ float g_bcu[128], g_bcv[128], g_bnu[128];
__device__ float g_W1y[64 * 64], g_b1y[64];
__device__ float g_W1a[64 * 64], g_b1a[64];

// --- monotonic float<->uint key for atomicMax over signed floats ---
__device__ __forceinline__ unsigned fkey(float f) {
    unsigned b = __float_as_uint(f);
    return (b & 0x80000000u) ? ~b : (b | 0x80000000u);
}
__device__ __forceinline__ float fdecode(unsigned k) {
    return __uint_as_float((k & 0x80000000u) ? (k ^ 0x80000000u) : ~k);
}

// ---------------------------------------------------------------------------
__global__ void init_k(int N) {
    int i = blockIdx.x * blockDim.x + threadIdx.x;
    if (i == 0) { g_maxkey = 0u; g_sum = 0.f; }
    int tot = N * 64;
    for (int j = i; j < tot; j += gridDim.x * blockDim.x) g_aggr64[j] = 0.f;
    for (int j = i; j < N; j += gridDim.x * blockDim.x) g_sp[j] = 0.f;
}

// ---------------------------------------------------------------------------
// ONE kernel for all composite weights (33280 outputs, K=128 dots)
// NOTE: g_bcu additionally folds in b_att1, so the edge kernel needs no b1.
// ---------------------------------------------------------------------------
__global__ void compose_all_k(const float* __restrict__ Wn, const float* __restrict__ bn,
                              const float* __restrict__ Watt, const float* __restrict__ batt1,
                              const float* __restrict__ Wupd,
                              const float* __restrict__ Wy1, const float* __restrict__ by1,
                              const float* __restrict__ Wa1, const float* __restrict__ ba1) {
    int id = blockIdx.x * blockDim.x + threadIdx.x;
    if (id < 24576) {                     // three [64,128] composites
        int sel = id >> 13, k = id & 8191, f = k >> 7, j = k & 127;
        const float* B = (sel == 0) ? Watt : (sel == 1) ? (Watt + 128 * 128) : Wupd;
        float* O = (sel == 0) ? g_Wcu : (sel == 1) ? g_Wcv : g_Wnu;
        float a = 0.f;
        for (int m = 0; m < 128; m++) a += Wn[f * 128 + m] * B[m * 128 + j];
        O[k] = a;
    } else if (id < 32768) {              // two [64,64] head composites
        int k = id - 24576, sel = k >> 12, kk = k & 4095, f = kk >> 6, j = kk & 63;
        const float* B = sel ? Wa1 : Wy1;
        float* O = sel ? g_W1a : g_W1y;
        float a = 0.f;
        for (int m = 0; m < 128; m++) a += Wn[f * 128 + m] * B[m * 64 + j];
        O[kk] = a;
    } else if (id < 33152) {              // three [128] bias composites
        int k = id - 32768, sel = k >> 7, j = k & 127;
        const float* B = (sel == 0) ? Watt : (sel == 1) ? (Watt + 128 * 128) : Wupd;
        float* O = (sel == 0) ? g_bcu : (sel == 1) ? g_bcv : g_bnu;
        float a = (sel == 0) ? batt1[j] : 0.f;   // fold b_att1 into bcu
        for (int m = 0; m < 128; m++) a += bn[m] * B[m * 128 + j];
        O[j] = a;
    } else if (id < 33280) {              // two [64] head biases
        int k = id - 33152, sel = k >> 6, j = k & 63;
        const float* B = sel ? Wa1 : Wy1;
        float a = sel ? ba1[j] : by1[j];
        for (int m = 0; m < 128; m++) a += bn[m] * B[m * 64 + j];
        (sel ? g_b1a : g_b1y)[j] = a;
    }
}

// ---------------------------------------------------------------------------
// Encoder: u,v [n,128] from mol_x [n,64] via composite weights.
// 256 threads: col = t&127, row-half = t>>7; 32-row tiles; acc[16].
// ---------------------------------------------------------------------------
__global__ void __launch_bounds__(256)
enc_k(const float* __restrict__ X, int n) {
    extern __shared__ float sm[];
    float* Ws = sm;            // 2 * 8192
    float* bs = sm + 16384;    // 2 * 128
    float* Xs = bs + 256;      // 32 * 64
    int t = threadIdx.x;
    int col = t & 127, half = t >> 7;
    for (int i = t; i < 2048; i += 256) ((float4*)Ws)[i]          = ((const float4*)g_Wcu)[i];
    for (int i = t; i < 2048; i += 256) ((float4*)(Ws + 8192))[i] = ((const float4*)g_Wcv)[i];
    if (t < 128) { bs[t] = g_bcu[t]; bs[128 + t] = g_bcv[t]; }

    for (int row0 = blockIdx.x * 32; row0 < n; row0 += gridDim.x * 32) {
        int nr = min(32, n - row0);
        __syncthreads();
        for (int i = t; i < nr * 16; i += 256)
            ((float4*)Xs)[i] = ((const float4*)(X + (size_t)row0 * 64))[i];
        __syncthreads();

#pragma unroll 1
        for (int g = 0; g < 2; g++) {
            const float* Wg = Ws + g * 8192;
            float acc[16];
#pragma unroll
            for (int r = 0; r < 16; r++) acc[r] = 0.f;
            for (int k4 = 0; k4 < 64; k4 += 4) {
                float w0 = Wg[(k4 + 0) * 128 + col];
                float w1 = Wg[(k4 + 1) * 128 + col];
                float w2 = Wg[(k4 + 2) * 128 + col];
                float w3 = Wg[(k4 + 3) * 128 + col];
#pragma unroll
                for (int r = 0; r < 16; r++) {
                    float4 xv = *(const float4*)&Xs[(half * 16 + r) * 64 + k4];
                    acc[r] += xv.x * w0 + xv.y * w1 + xv.z * w2 + xv.w * w3;
                }
            }
            float bv = bs[g * 128 + col];
            float* O = g ? g_v : g_u;
            int rmax = min(16, nr - half * 16);
            for (int r = 0; r < rmax; r++)
                O[(size_t)(row0 + half * 16 + r) * 128 + col] = acc[r] + bv;
        }
    }
}

// ---------------------------------------------------------------------------
// Edge attention score + fused global max. Persistent warps, TWO edges per
// iteration. Pos fetched by lanes 0-11 in ONE predicated LDG (<=4 L1
// wavefronts instead of 12 broadcasts), distributed via shuffles.
// b_att1 pre-folded into g_u (via bcu), so no bias term here.
// ---------------------------------------------------------------------------
__global__ void edge_k(const int* __restrict__ src, const int* __restrict__ dst,
                       const float* __restrict__ pos,
                       const float* __restrict__ Wd,
                       const float* __restrict__ W2, const float* __restrict__ b2,
                       int E) {
    int lane = threadIdx.x & 31;
    int wid = threadIdx.x >> 5;
    int gw = (blockIdx.x * blockDim.x + threadIdx.x) >> 5;
    int nw = (gridDim.x * blockDim.x) >> 5;

    float4 c0 = ((const float4*)Wd)[lane];
    float4 c1 = ((const float4*)(Wd + 128))[lane];
    float4 c2 = ((const float4*)(Wd + 256))[lane];
    float4 w2 = ((const float4*)W2)[lane];
    float b2v = b2[0];

    const unsigned FULL = 0xffffffffu;
    float wmax = -FLT_MAX;
    for (int e0 = gw * 2; e0 < E; e0 += 2 * nw) {
        int e1 = e0 + 1;
        bool has1 = e1 < E;                 // warp-uniform
        int e1c = has1 ? e1 : e0;           // clamped index (always valid)

        int sn0 = src[e0], dn0 = dst[e0];
        int sn1 = src[e1c], dn1 = dst[e1c];

        // issue all gathers first (maximize MLP)
        float4 a0 = ((const float4*)(g_u + (size_t)dn0 * 128))[lane];
        float4 j0 = ((const float4*)(g_v + (size_t)sn0 * 128))[lane];
        float4 a1 = ((const float4*)(g_u + (size_t)dn1 * 128))[lane];
        float4 j1 = ((const float4*)(g_v + (size_t)sn1 * 128))[lane];

        // pos: 12 floats fetched by lanes 0-11 in one LDG
        float pv = 0.f;
        if (lane < 12) {
            int sel = lane / 3, comp = lane - sel * 3;
            int node = (sel == 0) ? dn0 : (sel == 1) ? sn0 : (sel == 2) ? dn1 : sn1;
            pv = pos[node * 3 + comp];
        }
        float dx0 = __shfl_sync(FULL, pv, 0) - __shfl_sync(FULL, pv, 3);
        float dy0 = __shfl_sync(FULL, pv, 1) - __shfl_sync(FULL, pv, 4);
        float dz0 = __shfl_sync(FULL, pv, 2) - __shfl_sync(FULL, pv, 5);
        float dx1 = __shfl_sync(FULL, pv, 6) - __shfl_sync(FULL, pv, 9);
        float dy1 = __shfl_sync(FULL, pv, 7) - __shfl_sync(FULL, pv, 10);
        float dz1 = __shfl_sync(FULL, pv, 8) - __shfl_sync(FULL, pv, 11);

        float p0, p1;
        {
            float t0 = fmaxf(a0.x + j0.x + dx0 * c0.x + dy0 * c1.x + dz0 * c2.x, 0.f);
            float t1 = fmaxf(a0.y + j0.y + dx0 * c0.y + dy0 * c1.y + dz0 * c2.y, 0.f);
            float t2 = fmaxf(a0.z + j0.z + dx0 * c0.z + dy0 * c1.z + dz0 * c2.z, 0.f);
            float t3 = fmaxf(a0.w + j0.w + dx0 * c0.w + dy0 * c1.w + dz0 * c2.w, 0.f);
            p0 = t0 * w2.x + t1 * w2.y + t2 * w2.z + t3 * w2.w;
        }
        {
            float t0 = fmaxf(a1.x + j1.x + dx1 * c0.x + dy1 * c1.x + dz1 * c2.x, 0.f);
            float t1 = fmaxf(a1.y + j1.y + dx1 * c0.y + dy1 * c1.y + dz1 * c2.y, 0.f);
            float t2 = fmaxf(a1.z + j1.z + dx1 * c0.z + dy1 * c1.z + dz1 * c2.z, 0.f);
            float t3 = fmaxf(a1.w + j1.w + dx1 * c0.w + dy1 * c1.w + dz1 * c2.w, 0.f);
            p1 = t0 * w2.x + t1 * w2.y + t2 * w2.z + t3 * w2.w;
        }

        // interleaved independent shuffle chains
#pragma unroll
        for (int o = 16; o; o >>= 1) {
            p0 += __shfl_xor_sync(FULL, p0, o);
            p1 += __shfl_xor_sync(FULL, p1, o);
        }
        float s0 = p0 + b2v;
        float s1 = p1 + b2v;
        if (lane == 0) g_s[e0] = s0;
        wmax = fmaxf(wmax, s0);
        if (has1) {
            if (lane == 0) g_s[e1] = s1;
            wmax = fmaxf(wmax, s1);
        }
    }

    __shared__ float wm[8];
    if (lane == 0) wm[wid] = wmax;
    __syncthreads();
    if (threadIdx.x == 0) {
        float m = wm[0];
        for (int i = 1; i < (int)(blockDim.x >> 5); i++) m = fmaxf(m, wm[i]);
        atomicMax(&g_maxkey, fkey(m));
    }
}

// ---------------------------------------------------------------------------
// Fused exp + sum + 64-wide scatter. HALF-WARP (16 lanes) per edge.
// ---------------------------------------------------------------------------
__global__ void scatter_k(const int* __restrict__ src, const int* __restrict__ dst,
                          const float* __restrict__ molx, int E) {
    int tid = blockIdx.x * blockDim.x + threadIdx.x;
    int hw = tid >> 4;          // half-warp id = edge id
    int l16 = threadIdx.x & 15;

    float mx = fdecode(g_maxkey);
    float loc = 0.f;
    if (hw < E) {
        float p = expf(g_s[hw] - mx);
        int sn = src[hw], dn = dst[hw];
        float4 x = ((const float4*)(molx + (size_t)sn * 64))[l16];
        float* basep = g_aggr64 + (size_t)dn * 64 + l16 * 4;
        asm volatile("red.global.add.v4.f32 [%0], {%1, %2, %3, %4};"
                     :: "l"(basep), "f"(x.x * p), "f"(x.y * p), "f"(x.z * p), "f"(x.w * p)
                     : "memory");
        if (l16 == 0) {
            atomicAdd(&g_sp[dn], p);
            loc = p;
        }
    }
    for (int o = 16; o; o >>= 1) loc += __shfl_xor_sync(0xffffffffu, loc, o);
    __shared__ float ws[8];
    int lane = threadIdx.x & 31, wid = threadIdx.x >> 5;
    if (lane == 0) ws[wid] = loc;
    __syncthreads();
    if (threadIdx.x == 0) {
        float tot = 0.f;
        for (int i = 0; i < (int)(blockDim.x >> 5); i++) tot += ws[i];
        atomicAdd(&g_sum, tot);
    }
}

// ---------------------------------------------------------------------------
// Final GEMM (K=64): mol_feats = (aggr64@Wnu + sp*bnu)/sum + b_upd
// ---------------------------------------------------------------------------
__global__ void __launch_bounds__(256)
final_k(const float* __restrict__ bupd, float* __restrict__ Y, int n) {
    extern __shared__ float sm[];
    float* Ws = sm;            // 8192
    float* bs = sm + 8192;     // 2*128 (bnu, bupd)
    float* Xs = bs + 256;      // 32*64
    int t = threadIdx.x;
    int col = t & 127, half = t >> 7;
    for (int i = t; i < 2048; i += 256) ((float4*)Ws)[i] = ((const float4*)g_Wnu)[i];
    if (t < 128) { bs[t] = g_bnu[t]; bs[128 + t] = bupd[t]; }

    float is = 1.f / g_sum;

    for (int row0 = blockIdx.x * 32; row0 < n; row0 += gridDim.x * 32) {
        int nr = min(32, n - row0);
        __syncthreads();
        for (int i = t; i < nr * 16; i += 256)
            ((float4*)Xs)[i] = ((const float4*)(g_aggr64 + (size_t)row0 * 64))[i];
        __syncthreads();

        float acc[16];
#pragma unroll
        for (int r = 0; r < 16; r++) acc[r] = 0.f;
        for (int k4 = 0; k4 < 64; k4 += 4) {
            float w0 = Ws[(k4 + 0) * 128 + col];
            float w1 = Ws[(k4 + 1) * 128 + col];
            float w2 = Ws[(k4 + 2) * 128 + col];
            float w3 = Ws[(k4 + 3) * 128 + col];
#pragma unroll
            for (int r = 0; r < 16; r++) {
                float4 xv = *(const float4*)&Xs[(half * 16 + r) * 64 + k4];
                acc[r] += xv.x * w0 + xv.y * w1 + xv.z * w2 + xv.w * w3;
            }
        }
        float bnuv = bs[col], bupv = bs[128 + col];
        int rmax = min(16, nr - half * 16);
        for (int r = 0; r < rmax; r++) {
            int row = row0 + half * 16 + r;
            float sp = g_sp[row];
            Y[(size_t)row * 128 + col] = (acc[r] + sp * bnuv) * is + bupv;
        }
    }
}

// ---------------------------------------------------------------------------
// BOTH heads in one launch. Block picks (y) or (a) params by blockIdx.
// out[row] = relu(R[row]@W1c + b1c) @ W2 + b2
// ---------------------------------------------------------------------------
__global__ void heads_k(const float* __restrict__ Ry, const float* __restrict__ W2y,
                        const float* __restrict__ b2y, float* __restrict__ outY, int nY,
                        const float* __restrict__ Ra, const float* __restrict__ W2a,
                        const float* __restrict__ b2a, float* __restrict__ outA, int nA,
                        int blocksY) {
    __shared__ float W1s[64 * 64];
    __shared__ float b1s[64];
    __shared__ float W2s[64];
    __shared__ float rows[8][64];
    int t = threadIdx.x, lane = t & 31, wid = t >> 5;

    bool isY = blockIdx.x < blocksY;
    int bid = isY ? blockIdx.x : blockIdx.x - blocksY;
    const float* R   = isY ? Ry : Ra;
    const float* W1c = isY ? g_W1y : g_W1a;
    const float* b1c = isY ? g_b1y : g_b1a;
    const float* W2  = isY ? W2y : W2a;
    const float* b2  = isY ? b2y : b2a;
    float* out = isY ? outY : outA;
    int n = isY ? nY : nA;

    for (int i = t; i < 64 * 64; i += 256) W1s[i] = W1c[i];
    if (t < 64) { b1s[t] = b1c[t]; W2s[t] = W2[t]; }
    __syncthreads();
    float b2v = b2[0];
    int row = bid * 8 + wid;
    if (row < n) {
        if (lane < 16) ((float4*)rows[wid])[lane] = ((const float4*)(R + (size_t)row * 64))[lane];
        __syncwarp();
        float h0 = b1s[lane], h1 = b1s[lane + 32];
#pragma unroll 8
        for (int k = 0; k < 64; k++) {
            float x = rows[wid][k];
            h0 += x * W1s[k * 64 + lane];
            h1 += x * W1s[k * 64 + lane + 32];
        }
        float p = fmaxf(h0, 0.f) * W2s[lane] + fmaxf(h1, 0.f) * W2s[lane + 32];
        for (int o = 16; o; o >>= 1) p += __shfl_xor_sync(0xffffffffu, p, o);
        if (lane == 0) out[row] = p + b2v;
    }
}

// ---------------------------------------------------------------------------
extern "C" void kernel_launch(void* const* d_in, const int* in_sizes, int n_in,
                              void* d_out, int out_size) {
    const float* mol_x  = (const float*)d_in[0];
    const float* pos    = (const float*)d_in[1];
    const float* rx     = (const float*)d_in[2];
    const float* tx     = (const float*)d_in[3];
    const int*   ei     = (const int*)d_in[4];
    const float* W_node = (const float*)d_in[5];
    const float* b_node = (const float*)d_in[6];
    const float* W_att1 = (const float*)d_in[7];
    const float* b_att1 = (const float*)d_in[8];
    const float* W_att2 = (const float*)d_in[9];
    const float* b_att2 = (const float*)d_in[10];
    const float* W_upd  = (const float*)d_in[11];
    const float* b_upd  = (const float*)d_in[12];
    const float* Wy1 = (const float*)d_in[13];
    const float* by1 = (const float*)d_in[14];
    const float* Wy2 = (const float*)d_in[15];
    const float* by2 = (const float*)d_in[16];
    const float* Wa1 = (const float*)d_in[17];
    const float* ba1 = (const float*)d_in[18];
    const float* Wa2 = (const float*)d_in[19];
    const float* ba2 = (const float*)d_in[20];

    int N  = in_sizes[0] / 64;
    int NR = in_sizes[2] / 64;
    int NT = in_sizes[3] / 64;
    int E  = in_sizes[4] / 2;
    const int* srcP = ei;
    const int* dstP = ei + E;

    float* out   = (float*)d_out;
    float* out_y = out;             // pred_yield  [NR]
    float* out_a = out + NR;        // pred_activity [NT]
    float* out_m = out + NR + NT;   // mol_feats [N,128]

    int smem_enc   = (2 * 64 * 128 + 2 * 128 + 32 * 64) * 4;  // ~74 KB
    int smem_final = (64 * 128 + 2 * 128 + 32 * 64) * 4;      // ~42 KB
    cudaFuncSetAttribute(enc_k,   cudaFuncAttributeMaxDynamicSharedMemorySize, smem_enc);
    cudaFuncSetAttribute(final_k, cudaFuncAttributeMaxDynamicSharedMemorySize, smem_final);

    auto pgrid = [](int rows, int cap) {
        int tiles = (rows + 31) / 32;
        return tiles < cap ? tiles : cap;
    };

    init_k<<<256, 256>>>(N);
    compose_all_k<<<130, 256>>>(W_node, b_node, W_att1, b_att1, W_upd,
                                Wy1, by1, Wa1, ba1);

    // u, v from mol_x via composite weights (b_att1 folded into u's bias)
    enc_k<<<pgrid(N, 2 * 148), 256, smem_enc>>>(mol_x, N);

    // per-edge score + fused global max (persistent warps, 2-edge ILP,
    // lane-split pos gather)
    edge_k<<<592, 256>>>(srcP, dstP, pos, W_att1 + 256 * 128, W_att2, b_att2, E);

    // exp + sum + 64-wide scatter (half-warp per edge)
    scatter_k<<<(E * 16 + 255) / 256, 256>>>(srcP, dstP, mol_x, E);

    // final K=64 GEMM -> mol_feats
    final_k<<<pgrid(N, 4 * 148), 256, smem_final>>>(b_upd, out_m, N);

    // both heads in one launch
    int blocksY = (NR + 7) / 8, blocksA = (NT + 7) / 8;
    heads_k<<<blocksY + blocksA, 256>>>(rx, Wy2, by2, out_y, NR,
                                        tx, Wa2, ba2, out_a, NT, blocksY);
}

// round 12
// speedup vs baseline: 2.6909x; 1.0924x over previous
#include <cuda_runtime.h>
#include <math.h>
#include <float.h>

#define NMAX 50000
#define EMAX 400000

// Scratch (allocation-free rule: __device__ globals)
__device__ float g_u[NMAX * 128];
__device__ float g_v[NMAX * 128];
__device__ float g_aggr64[NMAX * 64];   // aggregated mol_x (64-wide)
__device__ float g_sp[NMAX];            // per-node sum of p
__device__ float g_s[EMAX];             // edge scores, then p=exp(s-max)
__device__ int   g_eid[EMAX];           // CSR edge ids
__device__ int   g_deg[NMAX];           // degree histogram
__device__ int   g_off[NMAX + 1];       // CSR offsets (mutated by fill)
__device__ int   g_bsum[64];            // scan block sums
__device__ unsigned int g_maxkey;
__device__ float g_sum;
// composite weights
__device__ float g_Wcu[64 * 128], g_Wcv[64 * 128], g_Wnu[64 * 128];
__device__ float g_bcu[128], g_bcv[128], g_bnu[128];
__device__ float g_W1y[64 * 64], g_b1y[64];
__device__ float g_W1a[64 * 64], g_b1a[64];

// --- monotonic float<->uint key for atomicMax over signed floats ---
__device__ __forceinline__ unsigned fkey(float f) {
    unsigned b = __float_as_uint(f);
    return (b & 0x80000000u) ? ~b : (b | 0x80000000u);
}
__device__ __forceinline__ float fdecode(unsigned k) {
    return __uint_as_float((k & 0x80000000u) ? (k ^ 0x80000000u) : ~k);
}

// ---------------------------------------------------------------------------
__global__ void init_k(int N) {
    int i = blockIdx.x * blockDim.x + threadIdx.x;
    if (i == 0) { g_maxkey = 0u; g_sum = 0.f; }
    for (int j = i; j < N; j += gridDim.x * blockDim.x) g_deg[j] = 0;
}

// ---------------------------------------------------------------------------
// ONE kernel for all composite weights. g_bcu folds in b_att1.
// ---------------------------------------------------------------------------
__global__ void compose_all_k(const float* __restrict__ Wn, const float* __restrict__ bn,
                              const float* __restrict__ Watt, const float* __restrict__ batt1,
                              const float* __restrict__ Wupd,
                              const float* __restrict__ Wy1, const float* __restrict__ by1,
                              const float* __restrict__ Wa1, const float* __restrict__ ba1) {
    int id = blockIdx.x * blockDim.x + threadIdx.x;
    if (id < 24576) {                     // three [64,128] composites
        int sel = id >> 13, k = id & 8191, f = k >> 7, j = k & 127;
        const float* B = (sel == 0) ? Watt : (sel == 1) ? (Watt + 128 * 128) : Wupd;
        float* O = (sel == 0) ? g_Wcu : (sel == 1) ? g_Wcv : g_Wnu;
        float a = 0.f;
        for (int m = 0; m < 128; m++) a += Wn[f * 128 + m] * B[m * 128 + j];
        O[k] = a;
    } else if (id < 32768) {              // two [64,64] head composites
        int k = id - 24576, sel = k >> 12, kk = k & 4095, f = kk >> 6, j = kk & 63;
        const float* B = sel ? Wa1 : Wy1;
        float* O = sel ? g_W1a : g_W1y;
        float a = 0.f;
        for (int m = 0; m < 128; m++) a += Wn[f * 128 + m] * B[m * 64 + j];
        O[kk] = a;
    } else if (id < 33152) {              // three [128] bias composites
        int k = id - 32768, sel = k >> 7, j = k & 127;
        const float* B = (sel == 0) ? Watt : (sel == 1) ? (Watt + 128 * 128) : Wupd;
        float* O = (sel == 0) ? g_bcu : (sel == 1) ? g_bcv : g_bnu;
        float a = (sel == 0) ? batt1[j] : 0.f;   // fold b_att1 into bcu
        for (int m = 0; m < 128; m++) a += bn[m] * B[m * 128 + j];
        O[j] = a;
    } else if (id < 33280) {              // two [64] head biases
        int k = id - 33152, sel = k >> 6, j = k & 63;
        const float* B = sel ? Wa1 : Wy1;
        float a = sel ? ba1[j] : by1[j];
        for (int m = 0; m < 128; m++) a += bn[m] * B[m * 64 + j];
        (sel ? g_b1a : g_b1y)[j] = a;
    }
}

// ---------------------------------------------------------------------------
// CSR build: histogram, 2-level parallel scan, fill
// ---------------------------------------------------------------------------
__global__ void hist_k(const int* __restrict__ dst, int E) {
    for (int i = blockIdx.x * blockDim.x + threadIdx.x; i < E; i += gridDim.x * blockDim.x)
        atomicAdd(&g_deg[dst[i]], 1);
}

// scanA: block b scans g_deg[b*1024 .. b*1024+1023] -> exclusive in g_off,
// block total -> g_bsum[b]
__global__ void scanA_k(int n) {
    __shared__ int wsum[32];
    int t = threadIdx.x, lane = t & 31, wid = t >> 5;
    int i = blockIdx.x * 1024 + t;
    int v = (i < n) ? g_deg[i] : 0;
    int x = v;
#pragma unroll
    for (int o = 1; o < 32; o <<= 1) {
        int y = __shfl_up_sync(0xffffffffu, x, o);
        if (lane >= o) x += y;
    }
    if (lane == 31) wsum[wid] = x;
    __syncthreads();
    if (wid == 0) {
        int w = wsum[lane];
#pragma unroll
        for (int o = 1; o < 32; o <<= 1) {
            int y = __shfl_up_sync(0xffffffffu, w, o);
            if (lane >= o) w += y;
        }
        wsum[lane] = w;
    }
    __syncthreads();
    int excl = (wid ? wsum[wid - 1] : 0) + x - v;
    if (i < n) g_off[i] = excl;
    if (t == 0) g_bsum[blockIdx.x] = wsum[31];
}

// scanB: exclusive scan of nb block sums (nb <= 64), single block
__global__ void scanB_k(int nb) {
    __shared__ int s[64];
    int t = threadIdx.x;
    if (t < nb) s[t] = g_bsum[t];
    __syncthreads();
    if (t == 0) {
        int acc = 0;
        for (int b = 0; b < nb; b++) { int v = s[b]; s[b] = acc; acc += v; }
    }
    __syncthreads();
    if (t < nb) g_bsum[t] = s[t];
}

// addoff: globalize per-block exclusive offsets
__global__ void addoff_k(int n) {
    int i = blockIdx.x * blockDim.x + threadIdx.x;
    if (i < n) g_off[i] += g_bsum[i >> 10];
}

// fill: p = exp(s-max) in place, accumulate g_sum, slot edges into CSR.
// atomicAdd on g_off itself: post-fill, g_off[d] == original g_off[d+1],
// so node d's range is [d ? g_off[d-1] : 0, g_off[d]).
__global__ void fill_k(const int* __restrict__ dst, int E) {
    float mx = fdecode(g_maxkey);
    float loc = 0.f;
    for (int i = blockIdx.x * blockDim.x + threadIdx.x; i < E; i += gridDim.x * blockDim.x) {
        float p = expf(g_s[i] - mx);
        g_s[i] = p;
        loc += p;
        int slot = atomicAdd(&g_off[dst[i]], 1);
        g_eid[slot] = i;
    }
    for (int o = 16; o; o >>= 1) loc += __shfl_xor_sync(0xffffffffu, loc, o);
    __shared__ float ws[8];
    int lane = threadIdx.x & 31, wid = threadIdx.x >> 5;
    if (lane == 0) ws[wid] = loc;
    __syncthreads();
    if (threadIdx.x == 0) {
        float tot = 0.f;
        for (int i = 0; i < (int)(blockDim.x >> 5); i++) tot += ws[i];
        atomicAdd(&g_sum, tot);
    }
}

// ---------------------------------------------------------------------------
// Encoder: u,v [n,128] from mol_x [n,64] via composite weights.
// ---------------------------------------------------------------------------
__global__ void __launch_bounds__(256)
enc_k(const float* __restrict__ X, int n) {
    extern __shared__ float sm[];
    float* Ws = sm;            // 2 * 8192
    float* bs = sm + 16384;    // 2 * 128
    float* Xs = bs + 256;      // 32 * 64
    int t = threadIdx.x;
    int col = t & 127, half = t >> 7;
    for (int i = t; i < 2048; i += 256) ((float4*)Ws)[i]          = ((const float4*)g_Wcu)[i];
    for (int i = t; i < 2048; i += 256) ((float4*)(Ws + 8192))[i] = ((const float4*)g_Wcv)[i];
    if (t < 128) { bs[t] = g_bcu[t]; bs[128 + t] = g_bcv[t]; }

    for (int row0 = blockIdx.x * 32; row0 < n; row0 += gridDim.x * 32) {
        int nr = min(32, n - row0);
        __syncthreads();
        for (int i = t; i < nr * 16; i += 256)
            ((float4*)Xs)[i] = ((const float4*)(X + (size_t)row0 * 64))[i];
        __syncthreads();

#pragma unroll 1
        for (int g = 0; g < 2; g++) {
            const float* Wg = Ws + g * 8192;
            float acc[16];
#pragma unroll
            for (int r = 0; r < 16; r++) acc[r] = 0.f;
            for (int k4 = 0; k4 < 64; k4 += 4) {
                float w0 = Wg[(k4 + 0) * 128 + col];
                float w1 = Wg[(k4 + 1) * 128 + col];
                float w2 = Wg[(k4 + 2) * 128 + col];
                float w3 = Wg[(k4 + 3) * 128 + col];
#pragma unroll
                for (int r = 0; r < 16; r++) {
                    float4 xv = *(const float4*)&Xs[(half * 16 + r) * 64 + k4];
                    acc[r] += xv.x * w0 + xv.y * w1 + xv.z * w2 + xv.w * w3;
                }
            }
            float bv = bs[g * 128 + col];
            float* O = g ? g_v : g_u;
            int rmax = min(16, nr - half * 16);
            for (int r = 0; r < rmax; r++)
                O[(size_t)(row0 + half * 16 + r) * 128 + col] = acc[r] + bv;
        }
    }
}

// ---------------------------------------------------------------------------
// Edge attention score + fused global max (persistent warps, 2-edge ILP,
// lane-split pos gather). b_att1 pre-folded into g_u.
// ---------------------------------------------------------------------------
__global__ void edge_k(const int* __restrict__ src, const int* __restrict__ dst,
                       const float* __restrict__ pos,
                       const float* __restrict__ Wd,
                       const float* __restrict__ W2, const float* __restrict__ b2,
                       int E) {
    int lane = threadIdx.x & 31;
    int wid = threadIdx.x >> 5;
    int gw = (blockIdx.x * blockDim.x + threadIdx.x) >> 5;
    int nw = (gridDim.x * blockDim.x) >> 5;

    float4 c0 = ((const float4*)Wd)[lane];
    float4 c1 = ((const float4*)(Wd + 128))[lane];
    float4 c2 = ((const float4*)(Wd + 256))[lane];
    float4 w2 = ((const float4*)W2)[lane];
    float b2v = b2[0];

    const unsigned FULL = 0xffffffffu;
    float wmax = -FLT_MAX;
    for (int e0 = gw * 2; e0 < E; e0 += 2 * nw) {
        int e1 = e0 + 1;
        bool has1 = e1 < E;                 // warp-uniform
        int e1c = has1 ? e1 : e0;           // clamped index (always valid)

        int sn0 = src[e0], dn0 = dst[e0];
        int sn1 = src[e1c], dn1 = dst[e1c];

        float4 a0 = ((const float4*)(g_u + (size_t)dn0 * 128))[lane];
        float4 j0 = ((const float4*)(g_v + (size_t)sn0 * 128))[lane];
        float4 a1 = ((const float4*)(g_u + (size_t)dn1 * 128))[lane];
        float4 j1 = ((const float4*)(g_v + (size_t)sn1 * 128))[lane];

        float pv = 0.f;
        if (lane < 12) {
            int sel = lane / 3, comp = lane - sel * 3;
            int node = (sel == 0) ? dn0 : (sel == 1) ? sn0 : (sel == 2) ? dn1 : sn1;
            pv = pos[node * 3 + comp];
        }
        float dx0 = __shfl_sync(FULL, pv, 0) - __shfl_sync(FULL, pv, 3);
        float dy0 = __shfl_sync(FULL, pv, 1) - __shfl_sync(FULL, pv, 4);
        float dz0 = __shfl_sync(FULL, pv, 2) - __shfl_sync(FULL, pv, 5);
        float dx1 = __shfl_sync(FULL, pv, 6) - __shfl_sync(FULL, pv, 9);
        float dy1 = __shfl_sync(FULL, pv, 7) - __shfl_sync(FULL, pv, 10);
        float dz1 = __shfl_sync(FULL, pv, 8) - __shfl_sync(FULL, pv, 11);

        float p0, p1;
        {
            float t0 = fmaxf(a0.x + j0.x + dx0 * c0.x + dy0 * c1.x + dz0 * c2.x, 0.f);
            float t1 = fmaxf(a0.y + j0.y + dx0 * c0.y + dy0 * c1.y + dz0 * c2.y, 0.f);
            float t2 = fmaxf(a0.z + j0.z + dx0 * c0.z + dy0 * c1.z + dz0 * c2.z, 0.f);
            float t3 = fmaxf(a0.w + j0.w + dx0 * c0.w + dy0 * c1.w + dz0 * c2.w, 0.f);
            p0 = t0 * w2.x + t1 * w2.y + t2 * w2.z + t3 * w2.w;
        }
        {
            float t0 = fmaxf(a1.x + j1.x + dx1 * c0.x + dy1 * c1.x + dz1 * c2.x, 0.f);
            float t1 = fmaxf(a1.y + j1.y + dx1 * c0.y + dy1 * c1.y + dz1 * c2.y, 0.f);
            float t2 = fmaxf(a1.z + j1.z + dx1 * c0.z + dy1 * c1.z + dz1 * c2.z, 0.f);
            float t3 = fmaxf(a1.w + j1.w + dx1 * c0.w + dy1 * c1.w + dz1 * c2.w, 0.f);
            p1 = t0 * w2.x + t1 * w2.y + t2 * w2.z + t3 * w2.w;
        }

#pragma unroll
        for (int o = 16; o; o >>= 1) {
            p0 += __shfl_xor_sync(FULL, p0, o);
            p1 += __shfl_xor_sync(FULL, p1, o);
        }
        float s0 = p0 + b2v;
        float s1 = p1 + b2v;
        if (lane == 0) g_s[e0] = s0;
        wmax = fmaxf(wmax, s0);
        if (has1) {
            if (lane == 0) g_s[e1] = s1;
            wmax = fmaxf(wmax, s1);
        }
    }

    __shared__ float wm[8];
    if (lane == 0) wm[wid] = wmax;
    __syncthreads();
    if (threadIdx.x == 0) {
        float m = wm[0];
        for (int i = 1; i < (int)(blockDim.x >> 5); i++) m = fmaxf(m, wm[i]);
        atomicMax(&g_maxkey, fkey(m));
    }
}

// ---------------------------------------------------------------------------
// Gather aggregation (atomic-free): HALF-WARP per node, register accumulate.
// aggr64[node] = sum_e mol_x[src[e]] * p[e] ; sp[node] = sum_e p[e]
// ---------------------------------------------------------------------------
__global__ void gather_k(const int* __restrict__ src, const float* __restrict__ molx,
                         int N) {
    int node = (blockIdx.x * blockDim.x + threadIdx.x) >> 4;
    int l16 = threadIdx.x & 15;
    if (node >= N) return;
    int beg = node ? g_off[node - 1] : 0;
    int end = g_off[node];
    float4 acc = make_float4(0.f, 0.f, 0.f, 0.f);
    float sp = 0.f;
    for (int i = beg; i < end; i++) {
        int e = g_eid[i];
        float p = g_s[e];
        int sn = src[e];
        float4 x = ((const float4*)(molx + (size_t)sn * 64))[l16];
        acc.x += x.x * p; acc.y += x.y * p; acc.z += x.z * p; acc.w += x.w * p;
        sp += p;
    }
    ((float4*)(g_aggr64 + (size_t)node * 64))[l16] = acc;
    if (l16 == 0) g_sp[node] = sp;
}

// ---------------------------------------------------------------------------
// Final GEMM (K=64): mol_feats = (aggr64@Wnu + sp*bnu)/sum + b_upd
// ---------------------------------------------------------------------------
__global__ void __launch_bounds__(256)
final_k(const float* __restrict__ bupd, float* __restrict__ Y, int n) {
    extern __shared__ float sm[];
    float* Ws = sm;            // 8192
    float* bs = sm + 8192;     // 2*128 (bnu, bupd)
    float* Xs = bs + 256;      // 32*64
    int t = threadIdx.x;
    int col = t & 127, half = t >> 7;
    for (int i = t; i < 2048; i += 256) ((float4*)Ws)[i] = ((const float4*)g_Wnu)[i];
    if (t < 128) { bs[t] = g_bnu[t]; bs[128 + t] = bupd[t]; }

    float is = 1.f / g_sum;

    for (int row0 = blockIdx.x * 32; row0 < n; row0 += gridDim.x * 32) {
        int nr = min(32, n - row0);
        __syncthreads();
        for (int i = t; i < nr * 16; i += 256)
            ((float4*)Xs)[i] = ((const float4*)(g_aggr64 + (size_t)row0 * 64))[i];
        __syncthreads();

        float acc[16];
#pragma unroll
        for (int r = 0; r < 16; r++) acc[r] = 0.f;
        for (int k4 = 0; k4 < 64; k4 += 4) {
            float w0 = Ws[(k4 + 0) * 128 + col];
            float w1 = Ws[(k4 + 1) * 128 + col];
            float w2 = Ws[(k4 + 2) * 128 + col];
            float w3 = Ws[(k4 + 3) * 128 + col];
#pragma unroll
            for (int r = 0; r < 16; r++) {
                float4 xv = *(const float4*)&Xs[(half * 16 + r) * 64 + k4];
                acc[r] += xv.x * w0 + xv.y * w1 + xv.z * w2 + xv.w * w3;
            }
        }
        float bnuv = bs[col], bupv = bs[128 + col];
        int rmax = min(16, nr - half * 16);
        for (int r = 0; r < rmax; r++) {
            int row = row0 + half * 16 + r;
            float sp = g_sp[row];
            Y[(size_t)row * 128 + col] = (acc[r] + sp * bnuv) * is + bupv;
        }
    }
}

// ---------------------------------------------------------------------------
// BOTH heads in one launch. Block picks (y) or (a) params by blockIdx.
// ---------------------------------------------------------------------------
__global__ void heads_k(const float* __restrict__ Ry, const float* __restrict__ W2y,
                        const float* __restrict__ b2y, float* __restrict__ outY, int nY,
                        const float* __restrict__ Ra, const float* __restrict__ W2a,
                        const float* __restrict__ b2a, float* __restrict__ outA, int nA,
                        int blocksY) {
    __shared__ float W1s[64 * 64];
    __shared__ float b1s[64];
    __shared__ float W2s[64];
    __shared__ float rows[8][64];
    int t = threadIdx.x, lane = t & 31, wid = t >> 5;

    bool isY = blockIdx.x < blocksY;
    int bid = isY ? blockIdx.x : blockIdx.x - blocksY;
    const float* R   = isY ? Ry : Ra;
    const float* W1c = isY ? g_W1y : g_W1a;
    const float* b1c = isY ? g_b1y : g_b1a;
    const float* W2  = isY ? W2y : W2a;
    const float* b2  = isY ? b2y : b2a;
    float* out = isY ? outY : outA;
    int n = isY ? nY : nA;

    for (int i = t; i < 64 * 64; i += 256) W1s[i] = W1c[i];
    if (t < 64) { b1s[t] = b1c[t]; W2s[t] = W2[t]; }
    __syncthreads();
    float b2v = b2[0];
    int row = bid * 8 + wid;
    if (row < n) {
        if (lane < 16) ((float4*)rows[wid])[lane] = ((const float4*)(R + (size_t)row * 64))[lane];
        __syncwarp();
        float h0 = b1s[lane], h1 = b1s[lane + 32];
#pragma unroll 8
        for (int k = 0; k < 64; k++) {
            float x = rows[wid][k];
            h0 += x * W1s[k * 64 + lane];
            h1 += x * W1s[k * 64 + lane + 32];
        }
        float p = fmaxf(h0, 0.f) * W2s[lane] + fmaxf(h1, 0.f) * W2s[lane + 32];
        for (int o = 16; o; o >>= 1) p += __shfl_xor_sync(0xffffffffu, p, o);
        if (lane == 0) out[row] = p + b2v;
    }
}

// ---------------------------------------------------------------------------
extern "C" void kernel_launch(void* const* d_in, const int* in_sizes, int n_in,
                              void* d_out, int out_size) {
    const float* mol_x  = (const float*)d_in[0];
    const float* pos    = (const float*)d_in[1];
    const float* rx     = (const float*)d_in[2];
    const float* tx     = (const float*)d_in[3];
    const int*   ei     = (const int*)d_in[4];
    const float* W_node = (const float*)d_in[5];
    const float* b_node = (const float*)d_in[6];
    const float* W_att1 = (const float*)d_in[7];
    const float* b_att1 = (const float*)d_in[8];
    const float* W_att2 = (const float*)d_in[9];
    const float* b_att2 = (const float*)d_in[10];
    const float* W_upd  = (const float*)d_in[11];
    const float* b_upd  = (const float*)d_in[12];
    const float* Wy1 = (const float*)d_in[13];
    const float* by1 = (const float*)d_in[14];
    const float* Wy2 = (const float*)d_in[15];
    const float* by2 = (const float*)d_in[16];
    const float* Wa1 = (const float*)d_in[17];
    const float* ba1 = (const float*)d_in[18];
    const float* Wa2 = (const float*)d_in[19];
    const float* ba2 = (const float*)d_in[20];

    int N  = in_sizes[0] / 64;
    int NR = in_sizes[2] / 64;
    int NT = in_sizes[3] / 64;
    int E  = in_sizes[4] / 2;
    const int* srcP = ei;
    const int* dstP = ei + E;

    float* out   = (float*)d_out;
    float* out_y = out;             // pred_yield  [NR]
    float* out_a = out + NR;        // pred_activity [NT]
    float* out_m = out + NR + NT;   // mol_feats [N,128]

    int smem_enc   = (2 * 64 * 128 + 2 * 128 + 32 * 64) * 4;  // ~74 KB
    int smem_final = (64 * 128 + 2 * 128 + 32 * 64) * 4;      // ~42 KB
    cudaFuncSetAttribute(enc_k,   cudaFuncAttributeMaxDynamicSharedMemorySize, smem_enc);
    cudaFuncSetAttribute(final_k, cudaFuncAttributeMaxDynamicSharedMemorySize, smem_final);

    auto pgrid = [](int rows, int cap) {
        int tiles = (rows + 31) / 32;
        return tiles < cap ? tiles : cap;
    };

    init_k<<<64, 256>>>(N);
    compose_all_k<<<130, 256>>>(W_node, b_node, W_att1, b_att1, W_upd,
                                Wy1, by1, Wa1, ba1);

    // CSR: histogram + 2-level parallel scan (independent of encoder)
    int nbScan = (N + 1023) / 1024;
    hist_k<<<592, 256>>>(dstP, E);
    scanA_k<<<nbScan, 1024>>>(N);
    scanB_k<<<1, 64>>>(nbScan);
    addoff_k<<<(N + 255) / 256, 256>>>(N);

    // u, v from mol_x via composite weights
    enc_k<<<pgrid(N, 2 * 148), 256, smem_enc>>>(mol_x, N);

    // per-edge score + fused global max
    edge_k<<<592, 256>>>(srcP, dstP, pos, W_att1 + 256 * 128, W_att2, b_att2, E);

    // exp + g_sum + CSR fill
    fill_k<<<592, 256>>>(dstP, E);

    // atomic-free gather aggregation (also produces g_sp)
    gather_k<<<(N * 16 + 255) / 256, 256>>>(srcP, mol_x, N);

    // final K=64 GEMM -> mol_feats
    final_k<<<pgrid(N, 4 * 148), 256, smem_final>>>(b_upd, out_m, N);

    // both heads in one launch
    int blocksY = (NR + 7) / 8, blocksA = (NT + 7) / 8;
    heads_k<<<blocksY + blocksA, 256>>>(rx, Wy2, by2, out_y, NR,
                                        tx, Wa2, ba2, out_a, NT, blocksY);
}